// round 1
// baseline (speedup 1.0000x reference)
#include <cuda_runtime.h>

// Problem constants (fixed shapes for this problem)
#define DD   256      // embedding dim
#define KK   8192     // num codes
#define NN   32768    // num query rows (16*2048)

#define BM   128
#define BN   128
#define BK   32
#define SMS  132      // smem row stride (pad 4 -> 16B-aligned rows, spread banks)

// Scratch (no allocations allowed)
__device__ float d_half_norm[KK];
__device__ int   d_usage[KK];
__device__ int   d_indices[NN];

// ---------------------------------------------------------------------------
// Kernel 1: half code norms + zero usage histogram
// grid = KK/8 blocks of 256 (8 warps -> 8 rows each)
// ---------------------------------------------------------------------------
__global__ void vq_norms_kernel(const float* __restrict__ emb) {
    int row  = blockIdx.x * 8 + (threadIdx.x >> 5);
    int lane = threadIdx.x & 31;
    const float* e = emb + (size_t)row * DD;
    float s = 0.f;
#pragma unroll
    for (int i = 0; i < 8; i++) {
        float v = e[lane + 32 * i];
        s += v * v;
    }
#pragma unroll
    for (int o = 16; o; o >>= 1) s += __shfl_xor_sync(0xffffffffu, s, o);
    if (lane == 0) d_half_norm[row] = 0.5f * s;

    int g = blockIdx.x * blockDim.x + threadIdx.x;
    if (g < KK) d_usage[g] = 0;
}

// ---------------------------------------------------------------------------
// Kernel 2: fused SGEMM + per-row argmin over all K codes.
// score(row, col) = 0.5*||e_col||^2 - x_row . e_col   (same argmin as reference)
// Block: 256 threads, 16x16 thread grid, 8x8 micro-tile each.
// grid = NN/BM = 256 CTAs -> one full wave at occupancy 2.
// ---------------------------------------------------------------------------
__global__ __launch_bounds__(256, 2)
void vq_argmin_kernel(const float* __restrict__ ze, const float* __restrict__ emb) {
    __shared__ __align__(16) float As[BK][SMS];
    __shared__ __align__(16) float Bs[BK][SMS];
    __shared__ float red_v[BM][16];
    __shared__ int   red_i[BM][16];

    const int tid = threadIdx.x;
    const int tx = tid & 15;        // col group
    const int ty = tid >> 4;        // row group
    const int m0 = blockIdx.x * BM;

    float minv[8];
    int   mini[8];
#pragma unroll
    for (int i = 0; i < 8; i++) { minv[i] = 3.4028235e38f; mini[i] = 0; }

    for (int n0 = 0; n0 < KK; n0 += BN) {
        float acc[8][8];
#pragma unroll
        for (int i = 0; i < 8; i++)
#pragma unroll
            for (int j = 0; j < 8; j++) acc[i][j] = 0.f;

        for (int d0 = 0; d0 < DD; d0 += BK) {
            __syncthreads();
            // Cooperative loads: 128x32 floats per tile = 4 float4 / thread each
#pragma unroll
            for (int s = 0; s < 4; s++) {
                int id = tid + 256 * s;
                int r  = id >> 3;            // 0..127
                int c4 = (id & 7) * 4;       // 0,4,..,28
                float4 av = *(const float4*)(ze  + (size_t)(m0 + r) * DD + d0 + c4);
                As[c4 + 0][r] = av.x; As[c4 + 1][r] = av.y;
                As[c4 + 2][r] = av.z; As[c4 + 3][r] = av.w;
                float4 bv = *(const float4*)(emb + (size_t)(n0 + r) * DD + d0 + c4);
                Bs[c4 + 0][r] = bv.x; Bs[c4 + 1][r] = bv.y;
                Bs[c4 + 2][r] = bv.z; Bs[c4 + 3][r] = bv.w;
            }
            __syncthreads();

#pragma unroll
            for (int k = 0; k < BK; k++) {
                float a[8], b[8];
                *(float4*)&a[0] = *(const float4*)&As[k][ty * 8];
                *(float4*)&a[4] = *(const float4*)&As[k][ty * 8 + 4];
                *(float4*)&b[0] = *(const float4*)&Bs[k][tx * 8];
                *(float4*)&b[4] = *(const float4*)&Bs[k][tx * 8 + 4];
#pragma unroll
                for (int i = 0; i < 8; i++)
#pragma unroll
                    for (int j = 0; j < 8; j++)
                        acc[i][j] += a[i] * b[j];
            }
        }

        // Epilogue for this col tile: fold into running argmin.
        // Iterate cols ascending + strict '<' => first-index tie semantics
        // within a thread; cross-thread ties broken by index in reduction.
#pragma unroll
        for (int j = 0; j < 8; j++) {
            int col = n0 + tx * 8 + j;
            float hn = d_half_norm[col];
#pragma unroll
            for (int i = 0; i < 8; i++) {
                float s = hn - acc[i][j];
                if (s < minv[i]) { minv[i] = s; mini[i] = col; }
            }
        }
    }

    __syncthreads();
#pragma unroll
    for (int i = 0; i < 8; i++) {
        red_v[ty * 8 + i][tx] = minv[i];
        red_i[ty * 8 + i][tx] = mini[i];
    }
    __syncthreads();

    if (tid < BM) {
        float bv = red_v[tid][0];
        int   bi = red_i[tid][0];
#pragma unroll
        for (int t = 1; t < 16; t++) {
            float v = red_v[tid][t];
            int  ix = red_i[tid][t];
            if (v < bv || (v == bv && ix < bi)) { bv = v; bi = ix; }
        }
        d_indices[m0 + tid] = bi;
        atomicAdd(&d_usage[bi], 1);
    }
}

// ---------------------------------------------------------------------------
// Kernel 3: gather z_q, compute z_q_st with the reference's rounding order,
// write indices as float. grid = NN blocks of 64 threads (4 floats each).
// out layout: [z_q_st (NN*DD) | z_q (NN*DD) | indices (NN) | stats (2)]
// ---------------------------------------------------------------------------
__global__ void vq_gather_kernel(const float* __restrict__ ze,
                                 const float* __restrict__ emb,
                                 float* __restrict__ out) {
    int m = blockIdx.x;
    int t = threadIdx.x;
    int idx = d_indices[m];

    float4 e = *(const float4*)(emb + (size_t)idx * DD + t * 4);
    float4 x = *(const float4*)(ze  + (size_t)m   * DD + t * 4);

    float4 st;
    st.x = x.x + (e.x - x.x);
    st.y = x.y + (e.y - x.y);
    st.z = x.z + (e.z - x.z);
    st.w = x.w + (e.w - x.w);

    *(float4*)(out + (size_t)m * DD + t * 4) = st;
    *(float4*)(out + (size_t)NN * DD + (size_t)m * DD + t * 4) = e;
    if (t == 0) out[(size_t)2 * NN * DD + m] = (float)idx;
}

// ---------------------------------------------------------------------------
// Kernel 4: perplexity + dead ratio. One block of 1024.
// total = sum(usage) = NN exactly; probs = u / 32768 (exact: pow2 divide).
// ---------------------------------------------------------------------------
__global__ void vq_stats_kernel(float* __restrict__ out) {
    __shared__ float sH[32];
    __shared__ int   sDead[32];
    int t = threadIdx.x;
    const float inv_total = 1.0f / (float)NN;

    float H = 0.f;
    int dead = 0;
    for (int k = t; k < KK; k += 1024) {
        int u = d_usage[k];
        if (u == 0) {
            dead++;
        } else {
            float p = (float)u * inv_total;
            H += p * logf(p);
        }
    }
#pragma unroll
    for (int o = 16; o; o >>= 1) {
        H    += __shfl_xor_sync(0xffffffffu, H, o);
        dead += __shfl_xor_sync(0xffffffffu, dead, o);
    }
    int warp = t >> 5, lane = t & 31;
    if (lane == 0) { sH[warp] = H; sDead[warp] = dead; }
    __syncthreads();
    if (t == 0) {
        float Ht = 0.f; int dt = 0;
        for (int w = 0; w < 32; w++) { Ht += sH[w]; dt += sDead[w]; }
        size_t off = (size_t)2 * NN * DD + NN;
        out[off + 0] = expf(-Ht);                    // perplexity
        out[off + 1] = (float)dt / (float)KK;        // dead_ratio
    }
}

// ---------------------------------------------------------------------------
extern "C" void kernel_launch(void* const* d_in, const int* in_sizes, int n_in,
                              void* d_out, int out_size) {
    const float* ze  = (const float*)d_in[0];   // [16,2048,256] fp32
    const float* emb = (const float*)d_in[1];   // [8192,256] fp32
    float* out = (float*)d_out;

    vq_norms_kernel<<<KK / 8, 256>>>(emb);
    vq_argmin_kernel<<<NN / BM, 256>>>(ze, emb);
    vq_gather_kernel<<<NN, 64>>>(ze, emb, out);
    vq_stats_kernel<<<1, 1024>>>(out);
}

// round 2
// speedup vs baseline: 1.0025x; 1.0025x over previous
#include <cuda_runtime.h>

// Problem constants (fixed shapes for this problem)
#define DD   256      // embedding dim
#define KK   8192     // num codes
#define NN   32768    // num query rows (16*2048)

#define BM   128
#define BN   128
#define BK   32
#define SMS  132      // smem row stride (pad 4 -> 16B-aligned rows, spread banks)

// Scratch (no allocations allowed)
__device__ float d_half_norm[KK];
__device__ int   d_usage[KK];
__device__ int   d_indices[NN];

// ---------------------------------------------------------------------------
// Kernel 1: half code norms + zero usage histogram
// grid = KK/8 blocks of 256 (8 warps -> 8 rows each)
// ---------------------------------------------------------------------------
__global__ void vq_norms_kernel(const float* __restrict__ emb) {
    int row  = blockIdx.x * 8 + (threadIdx.x >> 5);
    int lane = threadIdx.x & 31;
    const float* e = emb + (size_t)row * DD;
    float s = 0.f;
#pragma unroll
    for (int i = 0; i < 8; i++) {
        float v = e[lane + 32 * i];
        s += v * v;
    }
#pragma unroll
    for (int o = 16; o; o >>= 1) s += __shfl_xor_sync(0xffffffffu, s, o);
    if (lane == 0) d_half_norm[row] = 0.5f * s;

    int g = blockIdx.x * blockDim.x + threadIdx.x;
    if (g < KK) d_usage[g] = 0;
}

// ---------------------------------------------------------------------------
// Kernel 2: fused SGEMM + per-row argmin over all K codes.
// score(row, col) = 0.5*||e_col||^2 - x_row . e_col   (same argmin as reference)
// Block: 256 threads, 16x16 thread grid, 8x8 micro-tile each.
// grid = NN/BM = 256 CTAs -> one full wave at occupancy 2.
// ---------------------------------------------------------------------------
__global__ __launch_bounds__(256, 2)
void vq_argmin_kernel(const float* __restrict__ ze, const float* __restrict__ emb) {
    __shared__ __align__(16) float As[BK][SMS];
    __shared__ __align__(16) float Bs[BK][SMS];
    __shared__ float red_v[BM][16];
    __shared__ int   red_i[BM][16];

    const int tid = threadIdx.x;
    const int tx = tid & 15;        // col group
    const int ty = tid >> 4;        // row group
    const int m0 = blockIdx.x * BM;

    float minv[8];
    int   mini[8];
#pragma unroll
    for (int i = 0; i < 8; i++) { minv[i] = 3.4028235e38f; mini[i] = 0; }

    for (int n0 = 0; n0 < KK; n0 += BN) {
        float acc[8][8];
#pragma unroll
        for (int i = 0; i < 8; i++)
#pragma unroll
            for (int j = 0; j < 8; j++) acc[i][j] = 0.f;

        for (int d0 = 0; d0 < DD; d0 += BK) {
            __syncthreads();
            // Cooperative loads: 128x32 floats per tile = 4 float4 / thread each
#pragma unroll
            for (int s = 0; s < 4; s++) {
                int id = tid + 256 * s;
                int r  = id >> 3;            // 0..127
                int c4 = (id & 7) * 4;       // 0,4,..,28
                float4 av = *(const float4*)(ze  + (size_t)(m0 + r) * DD + d0 + c4);
                As[c4 + 0][r] = av.x; As[c4 + 1][r] = av.y;
                As[c4 + 2][r] = av.z; As[c4 + 3][r] = av.w;
                float4 bv = *(const float4*)(emb + (size_t)(n0 + r) * DD + d0 + c4);
                Bs[c4 + 0][r] = bv.x; Bs[c4 + 1][r] = bv.y;
                Bs[c4 + 2][r] = bv.z; Bs[c4 + 3][r] = bv.w;
            }
            __syncthreads();

#pragma unroll
            for (int k = 0; k < BK; k++) {
                float a[8], b[8];
                *(float4*)&a[0] = *(const float4*)&As[k][ty * 8];
                *(float4*)&a[4] = *(const float4*)&As[k][ty * 8 + 4];
                *(float4*)&b[0] = *(const float4*)&Bs[k][tx * 8];
                *(float4*)&b[4] = *(const float4*)&Bs[k][tx * 8 + 4];
#pragma unroll
                for (int i = 0; i < 8; i++)
#pragma unroll
                    for (int j = 0; j < 8; j++)
                        acc[i][j] += a[i] * b[j];
            }
        }

        // Epilogue for this col tile: fold into running argmin.
        // Iterate cols ascending + strict '<' => first-index tie semantics
        // within a thread; cross-thread ties broken by index in reduction.
#pragma unroll
        for (int j = 0; j < 8; j++) {
            int col = n0 + tx * 8 + j;
            float hn = d_half_norm[col];
#pragma unroll
            for (int i = 0; i < 8; i++) {
                float s = hn - acc[i][j];
                if (s < minv[i]) { minv[i] = s; mini[i] = col; }
            }
        }
    }

    __syncthreads();
#pragma unroll
    for (int i = 0; i < 8; i++) {
        red_v[ty * 8 + i][tx] = minv[i];
        red_i[ty * 8 + i][tx] = mini[i];
    }
    __syncthreads();

    if (tid < BM) {
        float bv = red_v[tid][0];
        int   bi = red_i[tid][0];
#pragma unroll
        for (int t = 1; t < 16; t++) {
            float v = red_v[tid][t];
            int  ix = red_i[tid][t];
            if (v < bv || (v == bv && ix < bi)) { bv = v; bi = ix; }
        }
        d_indices[m0 + tid] = bi;
        atomicAdd(&d_usage[bi], 1);
    }
}

// ---------------------------------------------------------------------------
// Kernel 3: gather z_q, compute z_q_st with the reference's rounding order,
// write indices as float. grid = NN blocks of 64 threads (4 floats each).
// out layout: [z_q_st (NN*DD) | z_q (NN*DD) | indices (NN) | stats (2)]
// ---------------------------------------------------------------------------
__global__ void vq_gather_kernel(const float* __restrict__ ze,
                                 const float* __restrict__ emb,
                                 float* __restrict__ out) {
    int m = blockIdx.x;
    int t = threadIdx.x;
    int idx = d_indices[m];

    float4 e = *(const float4*)(emb + (size_t)idx * DD + t * 4);
    float4 x = *(const float4*)(ze  + (size_t)m   * DD + t * 4);

    float4 st;
    st.x = x.x + (e.x - x.x);
    st.y = x.y + (e.y - x.y);
    st.z = x.z + (e.z - x.z);
    st.w = x.w + (e.w - x.w);

    *(float4*)(out + (size_t)m * DD + t * 4) = st;
    *(float4*)(out + (size_t)NN * DD + (size_t)m * DD + t * 4) = e;
    if (t == 0) out[(size_t)2 * NN * DD + m] = (float)idx;
}

// ---------------------------------------------------------------------------
// Kernel 4: perplexity + dead ratio. One block of 1024.
// total = sum(usage) = NN exactly; probs = u / 32768 (exact: pow2 divide).
// ---------------------------------------------------------------------------
__global__ void vq_stats_kernel(float* __restrict__ out) {
    __shared__ float sH[32];
    __shared__ int   sDead[32];
    int t = threadIdx.x;
    const float inv_total = 1.0f / (float)NN;

    float H = 0.f;
    int dead = 0;
    for (int k = t; k < KK; k += 1024) {
        int u = d_usage[k];
        if (u == 0) {
            dead++;
        } else {
            float p = (float)u * inv_total;
            H += p * logf(p);
        }
    }
#pragma unroll
    for (int o = 16; o; o >>= 1) {
        H    += __shfl_xor_sync(0xffffffffu, H, o);
        dead += __shfl_xor_sync(0xffffffffu, dead, o);
    }
    int warp = t >> 5, lane = t & 31;
    if (lane == 0) { sH[warp] = H; sDead[warp] = dead; }
    __syncthreads();
    if (t == 0) {
        float Ht = 0.f; int dt = 0;
        for (int w = 0; w < 32; w++) { Ht += sH[w]; dt += sDead[w]; }
        size_t off = (size_t)2 * NN * DD + NN;
        out[off + 0] = expf(-Ht);                    // perplexity
        out[off + 1] = (float)dt / (float)KK;        // dead_ratio
    }
}

// ---------------------------------------------------------------------------
extern "C" void kernel_launch(void* const* d_in, const int* in_sizes, int n_in,
                              void* d_out, int out_size) {
    const float* ze  = (const float*)d_in[0];   // [16,2048,256] fp32
    const float* emb = (const float*)d_in[1];   // [8192,256] fp32
    float* out = (float*)d_out;

    vq_norms_kernel<<<KK / 8, 256>>>(emb);
    vq_argmin_kernel<<<NN / BM, 256>>>(ze, emb);
    vq_gather_kernel<<<NN, 64>>>(ze, emb, out);
    vq_stats_kernel<<<1, 1024>>>(out);
}

// round 4
// speedup vs baseline: 2.3449x; 2.3391x over previous
#include <cuda_runtime.h>
#include <cuda_fp16.h>
#include <cstdint>

#define DD   256
#define KK   8192
#define NN   32768
#define CTAM 128
#define CTAN 256
#define NTILE  (KK / CTAN)        // 32
#define NCHUNK 16                 // K' = 1024 halves, 64 per chunk
#define NITER  (NTILE * NCHUNK)   // 512

// dynamic smem layout (bytes)
#define OFF_A  0                  // 8 planes x 16384 = 131072 (A' resident)
#define OFF_B  131072             // 2 stages x 32768 = 65536
#define OFF_HN 196608             // 256 floats
#define OFF_RV 197632             // 128*4 floats
#define OFF_RI 199680             // 128*4 ints
#define SMEM_TOTAL 201728

#define SWZ(x) ((x) ^ (((x) >> 3) & 0x70))

// Scratch (no allocations allowed)
__device__ float d_half_norm[KK];
__device__ int   d_usage[KK];
__device__ int   d_indices[NN];
__device__ __half d_A[(size_t)NN * 512];    // [a0(256) | a1(256)] per row, 32 MB
__device__ __half d_B[(size_t)KK * 1024];   // [b0 | b1 | b1 | b0] per row, 16 MB

__device__ __forceinline__ uint32_t smem_u32(const void* p) {
    uint32_t a;
    asm("{ .reg .u64 t; cvta.to.shared.u64 t, %1; cvt.u32.u64 %0, t; }" : "=r"(a) : "l"(p));
    return a;
}

// ---------------------------------------------------------------------------
// Exact 2-way fp16 split of queries / codes
// ---------------------------------------------------------------------------
__global__ void vq_split_ze(const float* __restrict__ src) {
    int i = blockIdx.x * blockDim.x + threadIdx.x;      // float2 units, NN*128
    float2 v = ((const float2*)src)[i];
    int r = i >> 7, kk = (i & 127) * 2;
    __half h0x = __float2half_rn(v.x);
    __half h1x = __float2half_rn(v.x - __half2float(h0x));
    __half h0y = __float2half_rn(v.y);
    __half h1y = __float2half_rn(v.y - __half2float(h0y));
    __half2* row = (__half2*)(d_A + (size_t)r * 512);
    row[kk >> 1]         = __halves2half2(h0x, h0y);
    row[(256 + kk) >> 1] = __halves2half2(h1x, h1y);
}
__global__ void vq_split_emb(const float* __restrict__ src) {
    int i = blockIdx.x * blockDim.x + threadIdx.x;      // float2 units, KK*128
    float2 v = ((const float2*)src)[i];
    int r = i >> 7, kk = (i & 127) * 2;
    __half h0x = __float2half_rn(v.x);
    __half h1x = __float2half_rn(v.x - __half2float(h0x));
    __half h0y = __float2half_rn(v.y);
    __half h1y = __float2half_rn(v.y - __half2float(h0y));
    __half2 b0 = __halves2half2(h0x, h0y);
    __half2 b1 = __halves2half2(h1x, h1y);
    __half2* row = (__half2*)(d_B + (size_t)r * 1024);
    row[kk >> 1]         = b0;   // seg0: b0
    row[(256 + kk) >> 1] = b1;   // seg1: b1
    row[(512 + kk) >> 1] = b1;   // seg2: b1
    row[(768 + kk) >> 1] = b0;   // seg3: b0
}

// ---------------------------------------------------------------------------
// half code norms (fp32 exact) + zero usage histogram
// ---------------------------------------------------------------------------
__global__ void vq_norms_kernel(const float* __restrict__ emb) {
    int row  = blockIdx.x * 8 + (threadIdx.x >> 5);
    int lane = threadIdx.x & 31;
    const float* e = emb + (size_t)row * DD;
    float s = 0.f;
#pragma unroll
    for (int i = 0; i < 8; i++) { float v = e[lane + 32 * i]; s += v * v; }
#pragma unroll
    for (int o = 16; o; o >>= 1) s += __shfl_xor_sync(0xffffffffu, s, o);
    if (lane == 0) d_half_norm[row] = 0.5f * s;
    int g = blockIdx.x * blockDim.x + threadIdx.x;
    if (g < KK) d_usage[g] = 0;
}

// ---------------------------------------------------------------------------
// HMMA split-GEMM + fused argmin.  256 CTAs x 256 threads, occ 1.
// ---------------------------------------------------------------------------
__global__ __launch_bounds__(256, 1) void vq_mma_kernel() {
    extern __shared__ __align__(1024) char smem[];
    const uint32_t sb = smem_u32(smem);
    const int tid  = threadIdx.x;
    const int lane = tid & 31, wid = tid >> 5;
    const int wm = wid >> 2, wn = wid & 3;      // 2m x 4n warp grid
    const int m0 = blockIdx.x * CTAM;
    float* shn = (float*)(smem + OFF_HN);

    // ---- A' resident load: 8 SW128 planes (plane p holds k' in [64p, 64p+64))
    {
        const __half* Arow = d_A + (size_t)m0 * 512;
#pragma unroll
        for (int q = 0; q < 32; ++q) {
            int i = tid + 256 * q;            // 0..8191 16B units
            int p = i >> 10;                  // plane
            int r = (i >> 3) & 127;           // row
            int u = i & 7;                    // 16B chunk in row
            uint4 v = *(const uint4*)(Arow + (size_t)r * 512 + p * 64 + u * 8);
            uint32_t off = (uint32_t)(p * 16384 + ((r >> 3) << 10) + ((r & 7) << 7) + (u << 4));
            *(uint4*)(smem + OFF_A + SWZ(off)) = v;
        }
    }

    float acc[4][8][4];
#pragma unroll
    for (int mi = 0; mi < 4; ++mi)
#pragma unroll
        for (int ni = 0; ni < 8; ++ni)
#pragma unroll
            for (int k = 0; k < 4; ++k) acc[mi][ni][k] = 0.f;
    float minv[8];
    int   mini[8];
#pragma unroll
    for (int i = 0; i < 8; ++i) { minv[i] = 3.4028235e38f; mini[i] = 0; }

    // ---- prime B pipeline
    {
        const __half* src = d_B;              // tile 0, chunk 0
        uint32_t db = sb + OFF_B;
#pragma unroll
        for (int j = 0; j < 8; ++j) {
            int i = tid + 256 * j;
            int r = i >> 3, u = i & 7;
            const void* gp = (const void*)(src + (size_t)r * 1024 + u * 8);
            uint32_t off = (uint32_t)(((r >> 3) << 10) + ((r & 7) << 7) + (u << 4));
            asm volatile("cp.async.cg.shared.global [%0], [%1], 16;"
                         :: "r"(db + SWZ(off)), "l"(gp));
        }
        asm volatile("cp.async.commit_group;" ::: "memory");
    }

    for (int g = 0; g < NITER; ++g) {
        const int c = g & 15;
        if (g + 1 < NITER) {
            const int g2 = g + 1;
            const __half* src = d_B + (size_t)((g2 >> 4) * CTAN) * 1024 + (g2 & 15) * 64;
            uint32_t db = sb + OFF_B + (uint32_t)(g2 & 1) * 32768;
#pragma unroll
            for (int j = 0; j < 8; ++j) {
                int i = tid + 256 * j;
                int r = i >> 3, u = i & 7;
                const void* gp = (const void*)(src + (size_t)r * 1024 + u * 8);
                uint32_t off = (uint32_t)(((r >> 3) << 10) + ((r & 7) << 7) + (u << 4));
                asm volatile("cp.async.cg.shared.global [%0], [%1], 16;"
                             :: "r"(db + SWZ(off)), "l"(gp));
            }
            asm volatile("cp.async.commit_group;" ::: "memory");
            asm volatile("cp.async.wait_group 1;" ::: "memory");
        } else {
            asm volatile("cp.async.wait_group 0;" ::: "memory");
        }
        __syncthreads();

        if (c == 0) shn[tid] = d_half_norm[(g >> 4) * CTAN + tid];

        const uint32_t ab = sb + OFF_A + (uint32_t)(c & 7) * 16384;
        const uint32_t bb = sb + OFF_B + (uint32_t)(g & 1) * 32768;
#pragma unroll
        for (int s = 0; s < 4; ++s) {
            uint32_t a[4][4];
#pragma unroll
            for (int mi = 0; mi < 4; ++mi) {
                int r = wm * 64 + mi * 16 + (lane & 7) + ((lane >> 3) & 1) * 8;
                int u = s * 2 + (lane >> 4);
                uint32_t off = ((uint32_t)(r >> 3) << 10) + ((uint32_t)(r & 7) << 7)
                             + ((uint32_t)u << 4);
                asm volatile("ldmatrix.sync.aligned.m8n8.x4.shared.b16 {%0,%1,%2,%3}, [%4];"
                    : "=r"(a[mi][0]), "=r"(a[mi][1]), "=r"(a[mi][2]), "=r"(a[mi][3])
                    : "r"(ab + SWZ(off)));
            }
            uint32_t b[8][2];
#pragma unroll
            for (int nq = 0; nq < 4; ++nq) {
                int r = wn * 64 + nq * 16 + (lane & 7) + ((lane >> 4) & 1) * 8;
                int u = s * 2 + ((lane >> 3) & 1);
                uint32_t off = ((uint32_t)(r >> 3) << 10) + ((uint32_t)(r & 7) << 7)
                             + ((uint32_t)u << 4);
                asm volatile("ldmatrix.sync.aligned.m8n8.x4.shared.b16 {%0,%1,%2,%3}, [%4];"
                    : "=r"(b[2*nq][0]), "=r"(b[2*nq][1]), "=r"(b[2*nq+1][0]), "=r"(b[2*nq+1][1])
                    : "r"(bb + SWZ(off)));
            }
#pragma unroll
            for (int mi = 0; mi < 4; ++mi)
#pragma unroll
                for (int ni = 0; ni < 8; ++ni)
                    asm volatile("mma.sync.aligned.m16n8k16.row.col.f32.f16.f16.f32 "
                        "{%0,%1,%2,%3}, {%4,%5,%6,%7}, {%8,%9}, {%0,%1,%2,%3};"
                        : "+f"(acc[mi][ni][0]), "+f"(acc[mi][ni][1]),
                          "+f"(acc[mi][ni][2]), "+f"(acc[mi][ni][3])
                        : "r"(a[mi][0]), "r"(a[mi][1]), "r"(a[mi][2]), "r"(a[mi][3]),
                          "r"(b[ni][0]), "r"(b[ni][1]));
        }

        if (c == 15) {
            const int tile = g >> 4;
#pragma unroll
            for (int ni = 0; ni < 8; ++ni)
#pragma unroll
                for (int c2 = 0; c2 < 2; ++c2) {
                    int coll = wn * 64 + ni * 8 + (lane & 3) * 2 + c2;
                    float hv = shn[coll];
                    int gcol = tile * CTAN + coll;
#pragma unroll
                    for (int mi = 0; mi < 4; ++mi)
#pragma unroll
                        for (int h = 0; h < 2; ++h) {
                            float sc = hv - acc[mi][ni][h * 2 + c2];
                            int rm = mi * 2 + h;
                            if (sc < minv[rm]) { minv[rm] = sc; mini[rm] = gcol; }
                            acc[mi][ni][h * 2 + c2] = 0.f;
                        }
                }
        }
        __syncthreads();
    }

    // ---- reduction: quad shuffle (same D-frag row), then across 4 n-warps
    float* rv = (float*)(smem + OFF_RV);
    int*   ri = (int*)(smem + OFF_RI);
#pragma unroll
    for (int rm = 0; rm < 8; ++rm) {
        float v = minv[rm]; int ix = mini[rm];
#pragma unroll
        for (int o = 1; o <= 2; o <<= 1) {
            float ov = __shfl_xor_sync(0xffffffffu, v, o);
            int   oi = __shfl_xor_sync(0xffffffffu, ix, o);
            if (ov < v || (ov == v && oi < ix)) { v = ov; ix = oi; }
        }
        if ((lane & 3) == 0) {
            int ml = wm * 64 + (rm >> 1) * 16 + (rm & 1) * 8 + (lane >> 2);
            rv[ml * 4 + wn] = v;
            ri[ml * 4 + wn] = ix;
        }
    }
    __syncthreads();
    if (tid < 128) {
        float v = rv[tid * 4]; int ix = ri[tid * 4];
#pragma unroll
        for (int w = 1; w < 4; ++w) {
            float ov = rv[tid * 4 + w]; int oi = ri[tid * 4 + w];
            if (ov < v || (ov == v && oi < ix)) { v = ov; ix = oi; }
        }
        d_indices[m0 + tid] = ix;
        atomicAdd(&d_usage[ix], 1);
    }
}

// ---------------------------------------------------------------------------
// gather + stats (unchanged from passing round-1 kernel)
// ---------------------------------------------------------------------------
__global__ void vq_gather_kernel(const float* __restrict__ ze,
                                 const float* __restrict__ emb,
                                 float* __restrict__ out) {
    int m = blockIdx.x, t = threadIdx.x;
    int idx = d_indices[m];
    float4 e = *(const float4*)(emb + (size_t)idx * DD + t * 4);
    float4 x = *(const float4*)(ze  + (size_t)m   * DD + t * 4);
    float4 st;
    st.x = x.x + (e.x - x.x); st.y = x.y + (e.y - x.y);
    st.z = x.z + (e.z - x.z); st.w = x.w + (e.w - x.w);
    *(float4*)(out + (size_t)m * DD + t * 4) = st;
    *(float4*)(out + (size_t)NN * DD + (size_t)m * DD + t * 4) = e;
    if (t == 0) out[(size_t)2 * NN * DD + m] = (float)idx;
}

__global__ void vq_stats_kernel(float* __restrict__ out) {
    __shared__ float sH[32];
    __shared__ int   sD[32];
    int t = threadIdx.x;
    float H = 0.f; int dead = 0;
    const float inv_total = 1.0f / (float)NN;
    for (int k = t; k < KK; k += 1024) {
        int u = d_usage[k];
        if (u == 0) dead++;
        else { float p = (float)u * inv_total; H += p * logf(p); }
    }
#pragma unroll
    for (int o = 16; o; o >>= 1) {
        H    += __shfl_xor_sync(0xffffffffu, H, o);
        dead += __shfl_xor_sync(0xffffffffu, dead, o);
    }
    if ((t & 31) == 0) { sH[t >> 5] = H; sD[t >> 5] = dead; }
    __syncthreads();
    if (t == 0) {
        float Ht = 0.f; int dt = 0;
        for (int w = 0; w < 32; w++) { Ht += sH[w]; dt += sD[w]; }
        size_t off = (size_t)2 * NN * DD + NN;
        out[off + 0] = expf(-Ht);
        out[off + 1] = (float)dt / (float)KK;
    }
}

// ---------------------------------------------------------------------------
extern "C" void kernel_launch(void* const* d_in, const int* in_sizes, int n_in,
                              void* d_out, int out_size) {
    const float* ze  = (const float*)d_in[0];
    const float* emb = (const float*)d_in[1];
    float* out = (float*)d_out;

    cudaFuncSetAttribute(vq_mma_kernel, cudaFuncAttributeMaxDynamicSharedMemorySize,
                         SMEM_TOTAL);

    vq_split_ze<<<NN * 128 / 256, 256>>>(ze);
    vq_split_emb<<<KK * 128 / 256, 256>>>(emb);
    vq_norms_kernel<<<KK / 8, 256>>>(emb);
    vq_mma_kernel<<<NN / CTAM, 256, SMEM_TOTAL>>>();
    vq_gather_kernel<<<NN, 64>>>(ze, emb, out);
    vq_stats_kernel<<<1, 1024>>>(out);
}

// round 5
// speedup vs baseline: 3.0376x; 1.2954x over previous
#include <cuda_runtime.h>
#include <cuda_fp16.h>
#include <cstdint>

#define DD   256
#define KK   8192
#define NN   32768
#define CTAM 128
#define CTAN 256
#define NTILE  (KK / CTAN)        // 32
#define NCHUNK 12                 // 3 products x 4 chunks of 64 halves
#define NITER  (NTILE * NCHUNK)   // 384

// dynamic smem layout (bytes)
#define OFF_A  0                  // 8 planes x 16384 = 131072 (A' = [a0|a1] resident)
#define OFF_B  131072             // 3 stages x 32768 = 98304
#define OFF_HN 229376             // 256 floats
#define SMEM_TOTAL 230400
// reduction scratch aliases the B ring after the mainloop
#define OFF_RV OFF_B
#define OFF_RI (OFF_B + 2048)

#define SWZ(x) ((x) ^ (((x) >> 3) & 0x70))

// Scratch (no allocations allowed)
__device__ float d_half_norm[KK];
__device__ int   d_usage[KK];
__device__ int   d_indices[NN];
__device__ __half d_A[(size_t)NN * 512];   // [a0(256) | a1(256)] per row, 32 MB
__device__ __half d_B[(size_t)KK * 512];   // [b0(256) | b1(256)] per row, 8 MB

__device__ __forceinline__ uint32_t smem_u32(const void* p) {
    uint32_t a;
    asm("{ .reg .u64 t; cvta.to.shared.u64 t, %1; cvt.u32.u64 %0, t; }" : "=r"(a) : "l"(p));
    return a;
}

// ---------------------------------------------------------------------------
// Exact 2-way fp16 splits
// ---------------------------------------------------------------------------
__global__ void vq_split_ze(const float* __restrict__ src) {
    int i = blockIdx.x * blockDim.x + threadIdx.x;      // float2 units
    float2 v = ((const float2*)src)[i];
    int r = i >> 7, kk = (i & 127) * 2;
    __half h0x = __float2half_rn(v.x);
    __half h1x = __float2half_rn(v.x - __half2float(h0x));
    __half h0y = __float2half_rn(v.y);
    __half h1y = __float2half_rn(v.y - __half2float(h0y));
    __half2* row = (__half2*)(d_A + (size_t)r * 512);
    row[kk >> 1]         = __halves2half2(h0x, h0y);
    row[(256 + kk) >> 1] = __halves2half2(h1x, h1y);
}
__global__ void vq_split_emb(const float* __restrict__ src) {
    int i = blockIdx.x * blockDim.x + threadIdx.x;
    float2 v = ((const float2*)src)[i];
    int r = i >> 7, kk = (i & 127) * 2;
    __half h0x = __float2half_rn(v.x);
    __half h1x = __float2half_rn(v.x - __half2float(h0x));
    __half h0y = __float2half_rn(v.y);
    __half h1y = __float2half_rn(v.y - __half2float(h0y));
    __half2* row = (__half2*)(d_B + (size_t)r * 512);
    row[kk >> 1]         = __halves2half2(h0x, h0y);   // b0
    row[(256 + kk) >> 1] = __halves2half2(h1x, h1y);   // b1
}

// ---------------------------------------------------------------------------
// half code norms (fp32 exact) + zero usage histogram
// ---------------------------------------------------------------------------
__global__ void vq_norms_kernel(const float* __restrict__ emb) {
    int row  = blockIdx.x * 8 + (threadIdx.x >> 5);
    int lane = threadIdx.x & 31;
    const float* e = emb + (size_t)row * DD;
    float s = 0.f;
#pragma unroll
    for (int i = 0; i < 8; i++) { float v = e[lane + 32 * i]; s += v * v; }
#pragma unroll
    for (int o = 16; o; o >>= 1) s += __shfl_xor_sync(0xffffffffu, s, o);
    if (lane == 0) d_half_norm[row] = 0.5f * s;
    int g = blockIdx.x * blockDim.x + threadIdx.x;
    if (g < KK) d_usage[g] = 0;
}

// ---------------------------------------------------------------------------
// HMMA split-GEMM + fused argmin.  256 CTAs x 256 threads, occ 1.
// Products: a0*b0 (chunks 0-3), a0*b1 (4-7), a1*b0 (8-11).
// ---------------------------------------------------------------------------
__device__ __forceinline__ void issue_b_chunk(uint32_t sb, int g2, int tid) {
    const int t2 = g2 / NCHUNK;
    const int c2 = g2 - t2 * NCHUNK;
    const int seg = (c2 < 8) ? c2 : (c2 - 8);           // 64-half unit in [b0|b1]
    const __half* src = d_B + (size_t)(t2 * CTAN) * 512 + seg * 64;
    uint32_t db = sb + OFF_B + (uint32_t)(g2 % 3) * 32768;
#pragma unroll
    for (int j = 0; j < 8; ++j) {
        int i = tid + 256 * j;
        int r = i >> 3, u = i & 7;
        const void* gp = (const void*)(src + (size_t)r * 512 + u * 8);
        uint32_t off = (uint32_t)(((r >> 3) << 10) + ((r & 7) << 7) + (u << 4));
        asm volatile("cp.async.cg.shared.global [%0], [%1], 16;"
                     :: "r"(db + SWZ(off)), "l"(gp));
    }
    asm volatile("cp.async.commit_group;" ::: "memory");
}

__global__ __launch_bounds__(256, 1) void vq_mma_kernel() {
    extern __shared__ __align__(1024) char smem[];
    const uint32_t sb = smem_u32(smem);
    const int tid  = threadIdx.x;
    const int lane = tid & 31, wid = tid >> 5;
    const int wm = wid >> 2, wn = wid & 3;      // 2m x 4n warp grid
    const int m0 = blockIdx.x * CTAM;
    float* shn = (float*)(smem + OFF_HN);

    // ---- A' resident: 8 SW128 planes; plane p = halves [64p, 64p+64)
    {
        const __half* Arow = d_A + (size_t)m0 * 512;
#pragma unroll
        for (int q = 0; q < 32; ++q) {
            int i = tid + 256 * q;            // 0..8191 16B units
            int p = i >> 10;
            int r = (i >> 3) & 127;
            int u = i & 7;
            uint4 v = *(const uint4*)(Arow + (size_t)r * 512 + p * 64 + u * 8);
            uint32_t off = (uint32_t)(p * 16384 + ((r >> 3) << 10) + ((r & 7) << 7) + (u << 4));
            *(uint4*)(smem + OFF_A + SWZ(off)) = v;
        }
    }

    float acc[4][8][4];
#pragma unroll
    for (int mi = 0; mi < 4; ++mi)
#pragma unroll
        for (int ni = 0; ni < 8; ++ni)
#pragma unroll
            for (int k = 0; k < 4; ++k) acc[mi][ni][k] = 0.f;
    float minv[8];
    int   mini[8];
#pragma unroll
    for (int i = 0; i < 8; ++i) { minv[i] = 3.4028235e38f; mini[i] = 0; }

    // ---- prime 2 stages
    issue_b_chunk(sb, 0, tid);
    issue_b_chunk(sb, 1, tid);

    int tile = 0, c = 0;
    for (int g = 0; g < NITER; ++g) {
        __syncthreads();                       // stage (g+2)%3 free everywhere
        if (g + 2 < NITER) {
            issue_b_chunk(sb, g + 2, tid);
            asm volatile("cp.async.wait_group 2;" ::: "memory");
        } else if (g + 1 < NITER) {
            asm volatile("cp.async.wait_group 1;" ::: "memory");
        } else {
            asm volatile("cp.async.wait_group 0;" ::: "memory");
        }
        __syncthreads();                       // stage g%3 data visible

        if (c == 0) shn[tid] = d_half_norm[tile * CTAN + tid];

        const int apl = (c < 8) ? (c & 3) : (c - 4);   // a0 planes 0-3, a1 planes 4-7
        const uint32_t ab = sb + OFF_A + (uint32_t)apl * 16384;
        const uint32_t bb = sb + OFF_B + (uint32_t)(g % 3) * 32768;
#pragma unroll
        for (int s = 0; s < 4; ++s) {
            uint32_t a[4][4];
#pragma unroll
            for (int mi = 0; mi < 4; ++mi) {
                int r = wm * 64 + mi * 16 + (lane & 7) + ((lane >> 3) & 1) * 8;
                int u = s * 2 + (lane >> 4);
                uint32_t off = ((uint32_t)(r >> 3) << 10) + ((uint32_t)(r & 7) << 7)
                             + ((uint32_t)u << 4);
                asm volatile("ldmatrix.sync.aligned.m8n8.x4.shared.b16 {%0,%1,%2,%3}, [%4];"
                    : "=r"(a[mi][0]), "=r"(a[mi][1]), "=r"(a[mi][2]), "=r"(a[mi][3])
                    : "r"(ab + SWZ(off)));
            }
            uint32_t b[8][2];
#pragma unroll
            for (int nq = 0; nq < 4; ++nq) {
                int r = wn * 64 + nq * 16 + (lane & 7) + ((lane >> 4) & 1) * 8;
                int u = s * 2 + ((lane >> 3) & 1);
                uint32_t off = ((uint32_t)(r >> 3) << 10) + ((uint32_t)(r & 7) << 7)
                             + ((uint32_t)u << 4);
                asm volatile("ldmatrix.sync.aligned.m8n8.x4.shared.b16 {%0,%1,%2,%3}, [%4];"
                    : "=r"(b[2*nq][0]), "=r"(b[2*nq][1]), "=r"(b[2*nq+1][0]), "=r"(b[2*nq+1][1])
                    : "r"(bb + SWZ(off)));
            }
#pragma unroll
            for (int mi = 0; mi < 4; ++mi)
#pragma unroll
                for (int ni = 0; ni < 8; ++ni)
                    asm volatile("mma.sync.aligned.m16n8k16.row.col.f32.f16.f16.f32 "
                        "{%0,%1,%2,%3}, {%4,%5,%6,%7}, {%8,%9}, {%0,%1,%2,%3};"
                        : "+f"(acc[mi][ni][0]), "+f"(acc[mi][ni][1]),
                          "+f"(acc[mi][ni][2]), "+f"(acc[mi][ni][3])
                        : "r"(a[mi][0]), "r"(a[mi][1]), "r"(a[mi][2]), "r"(a[mi][3]),
                          "r"(b[ni][0]), "r"(b[ni][1]));
        }

        if (c == NCHUNK - 1) {
#pragma unroll
            for (int ni = 0; ni < 8; ++ni)
#pragma unroll
                for (int c2 = 0; c2 < 2; ++c2) {
                    int coll = wn * 64 + ni * 8 + (lane & 3) * 2 + c2;
                    float hv = shn[coll];
                    int gcol = tile * CTAN + coll;
#pragma unroll
                    for (int mi = 0; mi < 4; ++mi)
#pragma unroll
                        for (int h = 0; h < 2; ++h) {
                            float sc = hv - acc[mi][ni][h * 2 + c2];
                            int rm = mi * 2 + h;
                            if (sc < minv[rm]) { minv[rm] = sc; mini[rm] = gcol; }
                            acc[mi][ni][h * 2 + c2] = 0.f;
                        }
                }
            tile++; c = 0;
        } else {
            c++;
        }
    }

    // ---- reduction (scratch aliases B ring; all compute done)
    __syncthreads();
    float* rv = (float*)(smem + OFF_RV);
    int*   ri = (int*)(smem + OFF_RI);
#pragma unroll
    for (int rm = 0; rm < 8; ++rm) {
        float v = minv[rm]; int ix = mini[rm];
#pragma unroll
        for (int o = 1; o <= 2; o <<= 1) {
            float ov = __shfl_xor_sync(0xffffffffu, v, o);
            int   oi = __shfl_xor_sync(0xffffffffu, ix, o);
            if (ov < v || (ov == v && oi < ix)) { v = ov; ix = oi; }
        }
        if ((lane & 3) == 0) {
            int ml = wm * 64 + (rm >> 1) * 16 + (rm & 1) * 8 + (lane >> 2);
            rv[ml * 4 + wn] = v;
            ri[ml * 4 + wn] = ix;
        }
    }
    __syncthreads();
    if (tid < 128) {
        float v = rv[tid * 4]; int ix = ri[tid * 4];
#pragma unroll
        for (int w = 1; w < 4; ++w) {
            float ov = rv[tid * 4 + w]; int oi = ri[tid * 4 + w];
            if (ov < v || (ov == v && oi < ix)) { v = ov; ix = oi; }
        }
        d_indices[m0 + tid] = ix;
        atomicAdd(&d_usage[ix], 1);
    }
}

// ---------------------------------------------------------------------------
// gather + stats
// ---------------------------------------------------------------------------
__global__ void vq_gather_kernel(const float* __restrict__ ze,
                                 const float* __restrict__ emb,
                                 float* __restrict__ out) {
    int m = blockIdx.x, t = threadIdx.x;
    int idx = d_indices[m];
    float4 e = *(const float4*)(emb + (size_t)idx * DD + t * 4);
    float4 x = *(const float4*)(ze  + (size_t)m   * DD + t * 4);
    float4 st;
    st.x = x.x + (e.x - x.x); st.y = x.y + (e.y - x.y);
    st.z = x.z + (e.z - x.z); st.w = x.w + (e.w - x.w);
    *(float4*)(out + (size_t)m * DD + t * 4) = st;
    *(float4*)(out + (size_t)NN * DD + (size_t)m * DD + t * 4) = e;
    if (t == 0) out[(size_t)2 * NN * DD + m] = (float)idx;
}

__global__ void vq_stats_kernel(float* __restrict__ out) {
    __shared__ float sH[32];
    __shared__ int   sD[32];
    int t = threadIdx.x;
    float H = 0.f; int dead = 0;
    const float inv_total = 1.0f / (float)NN;
    for (int k = t; k < KK; k += 1024) {
        int u = d_usage[k];
        if (u == 0) dead++;
        else { float p = (float)u * inv_total; H += p * logf(p); }
    }
#pragma unroll
    for (int o = 16; o; o >>= 1) {
        H    += __shfl_xor_sync(0xffffffffu, H, o);
        dead += __shfl_xor_sync(0xffffffffu, dead, o);
    }
    if ((t & 31) == 0) { sH[t >> 5] = H; sD[t >> 5] = dead; }
    __syncthreads();
    if (t == 0) {
        float Ht = 0.f; int dt = 0;
        for (int w = 0; w < 32; w++) { Ht += sH[w]; dt += sD[w]; }
        size_t off = (size_t)2 * NN * DD + NN;
        out[off + 0] = expf(-Ht);
        out[off + 1] = (float)dt / (float)KK;
    }
}

// ---------------------------------------------------------------------------
extern "C" void kernel_launch(void* const* d_in, const int* in_sizes, int n_in,
                              void* d_out, int out_size) {
    const float* ze  = (const float*)d_in[0];
    const float* emb = (const float*)d_in[1];
    float* out = (float*)d_out;

    cudaFuncSetAttribute(vq_mma_kernel, cudaFuncAttributeMaxDynamicSharedMemorySize,
                         SMEM_TOTAL);

    vq_split_ze<<<NN * 128 / 256, 256>>>(ze);
    vq_split_emb<<<KK * 128 / 256, 256>>>(emb);
    vq_norms_kernel<<<KK / 8, 256>>>(emb);
    vq_mma_kernel<<<NN / CTAM, 256, SMEM_TOTAL>>>();
    vq_gather_kernel<<<NN, 64>>>(ze, emb, out);
    vq_stats_kernel<<<1, 1024>>>(out);
}

// round 6
// speedup vs baseline: 4.3006x; 1.4158x over previous
#include <cuda_runtime.h>
#include <cuda_fp16.h>
#include <cstdint>

#define DD   256
#define KK   8192
#define NN   32768
#define CTAM 128
#define CTAN 256
#define NSPLIT 4                  // rescue N-splits (2048 codes each)

// ---- pass1 smem layout (A = a0 only, 4 planes)
#define P1_OFF_A  0               // 4 x 16384 = 65536
#define P1_OFF_B  65536           // 3 stages x 32768 = 98304
#define P1_OFF_HN 163840          // 256 floats
#define P1_SMEM   164864
#define P1_OFF_RV P1_OFF_B
#define P1_OFF_RI (P1_OFF_B + 2048)
#define P1_OFF_R2 (P1_OFF_B + 4096)

// ---- rescue smem layout (A = [a0|a1], 8 planes)
#define RS_OFF_A  0               // 8 x 16384 = 131072
#define RS_OFF_B  131072          // 3 stages x 32768
#define RS_OFF_HN 229376
#define RS_SMEM   230400
#define RS_OFF_RV RS_OFF_B
#define RS_OFF_RI (RS_OFF_B + 2048)

#define SWZ(x) ((x) ^ (((x) >> 3) & 0x70))

// Scratch (no allocations allowed)
__device__ float d_half_norm[KK];
__device__ float d_xnorm[NN];
__device__ int   d_usage[KK];
__device__ int   d_indices[NN];
__device__ int   d_count;
__device__ int   d_emax_bits;
__device__ int   d_amb[NN];
__device__ float d_resc_v[NSPLIT * NN];
__device__ int   d_resc_i[NSPLIT * NN];
__device__ __half d_A[(size_t)NN * 512];   // [a0(256) | a1(256)] per row
__device__ __half d_B[(size_t)KK * 512];   // [b0(256) | b1(256)] per row

__device__ __forceinline__ uint32_t smem_u32(const void* p) {
    uint32_t a;
    asm("{ .reg .u64 t; cvta.to.shared.u64 t, %1; cvt.u32.u64 %0, t; }" : "=r"(a) : "l"(p));
    return a;
}

// ---------------------------------------------------------------------------
// splits (exact 2-way fp16) + per-launch state reset
// ---------------------------------------------------------------------------
__global__ void vq_split_ze(const float* __restrict__ src) {
    if (blockIdx.x == 0 && threadIdx.x == 0) { d_count = 0; d_emax_bits = 0; }
    int i = blockIdx.x * blockDim.x + threadIdx.x;      // float2 units
    float2 v = ((const float2*)src)[i];
    int r = i >> 7, kk = (i & 127) * 2;
    __half h0x = __float2half_rn(v.x);
    __half h1x = __float2half_rn(v.x - __half2float(h0x));
    __half h0y = __float2half_rn(v.y);
    __half h1y = __float2half_rn(v.y - __half2float(h0y));
    __half2* row = (__half2*)(d_A + (size_t)r * 512);
    row[kk >> 1]         = __halves2half2(h0x, h0y);
    row[(256 + kk) >> 1] = __halves2half2(h1x, h1y);
}
__global__ void vq_split_emb(const float* __restrict__ src) {
    int i = blockIdx.x * blockDim.x + threadIdx.x;
    float2 v = ((const float2*)src)[i];
    int r = i >> 7, kk = (i & 127) * 2;
    __half h0x = __float2half_rn(v.x);
    __half h1x = __float2half_rn(v.x - __half2float(h0x));
    __half h0y = __float2half_rn(v.y);
    __half h1y = __float2half_rn(v.y - __half2float(h0y));
    __half2* row = (__half2*)(d_B + (size_t)r * 512);
    row[kk >> 1]         = __halves2half2(h0x, h0y);
    row[(256 + kk) >> 1] = __halves2half2(h1x, h1y);
}

// ---------------------------------------------------------------------------
// norms: hn + max code norm + usage reset; query row norms
// ---------------------------------------------------------------------------
__global__ void vq_norms_kernel(const float* __restrict__ emb) {
    int row  = blockIdx.x * 8 + (threadIdx.x >> 5);
    int lane = threadIdx.x & 31;
    const float* e = emb + (size_t)row * DD;
    float s = 0.f;
#pragma unroll
    for (int i = 0; i < 8; i++) { float v = e[lane + 32 * i]; s += v * v; }
#pragma unroll
    for (int o = 16; o; o >>= 1) s += __shfl_xor_sync(0xffffffffu, s, o);
    if (lane == 0) {
        d_half_norm[row] = 0.5f * s;
        atomicMax(&d_emax_bits, __float_as_int(sqrtf(s)));
    }
    int g = blockIdx.x * blockDim.x + threadIdx.x;
    if (g < KK) d_usage[g] = 0;
}
__global__ void vq_xnorm_kernel(const float* __restrict__ ze) {
    int row  = blockIdx.x * 8 + (threadIdx.x >> 5);
    int lane = threadIdx.x & 31;
    const float* x = ze + (size_t)row * DD;
    float s = 0.f;
#pragma unroll
    for (int i = 0; i < 8; i++) { float v = x[lane + 32 * i]; s += v * v; }
#pragma unroll
    for (int o = 16; o; o >>= 1) s += __shfl_xor_sync(0xffffffffu, s, o);
    if (lane == 0) d_xnorm[row] = sqrtf(s);
}

// ---------------------------------------------------------------------------
// Pass 1: single-product (a0*b0) GEMM + min1/min2 tracking + certification
// ---------------------------------------------------------------------------
__device__ __forceinline__ void p1_issue_b(uint32_t sb, int g2, int tid) {
    const int t2 = g2 >> 2, seg = g2 & 3;               // b0 segs 0-3
    const __half* src = d_B + (size_t)(t2 * CTAN) * 512 + seg * 64;
    uint32_t db = sb + P1_OFF_B + (uint32_t)(g2 % 3) * 32768;
#pragma unroll
    for (int j = 0; j < 8; ++j) {
        int i = tid + 256 * j;
        int r = i >> 3, u = i & 7;
        const void* gp = (const void*)(src + (size_t)r * 512 + u * 8);
        uint32_t off = (uint32_t)(((r >> 3) << 10) + ((r & 7) << 7) + (u << 4));
        asm volatile("cp.async.cg.shared.global [%0], [%1], 16;"
                     :: "r"(db + SWZ(off)), "l"(gp));
    }
    asm volatile("cp.async.commit_group;" ::: "memory");
}

__global__ __launch_bounds__(256, 1) void vq_pass1_kernel() {
    extern __shared__ __align__(1024) char smem[];
    const uint32_t sb = smem_u32(smem);
    const int tid  = threadIdx.x;
    const int lane = tid & 31, wid = tid >> 5;
    const int wm = wid >> 2, wn = wid & 3;
    const int m0 = blockIdx.x * CTAM;
    float* shn = (float*)(smem + P1_OFF_HN);

    // A resident: a0 only, 4 planes
    {
        const __half* Arow = d_A + (size_t)m0 * 512;
#pragma unroll
        for (int q = 0; q < 16; ++q) {
            int i = tid + 256 * q;            // 0..4095 16B units
            int p = i >> 10;
            int r = (i >> 3) & 127;
            int u = i & 7;
            uint4 v = *(const uint4*)(Arow + (size_t)r * 512 + p * 64 + u * 8);
            uint32_t off = (uint32_t)(p * 16384 + ((r >> 3) << 10) + ((r & 7) << 7) + (u << 4));
            *(uint4*)(smem + P1_OFF_A + SWZ(off)) = v;
        }
    }

    float acc[4][8][4];
#pragma unroll
    for (int mi = 0; mi < 4; ++mi)
#pragma unroll
        for (int ni = 0; ni < 8; ++ni)
#pragma unroll
            for (int k = 0; k < 4; ++k) acc[mi][ni][k] = 0.f;
    float m1[8], m2[8];
    int   i1[8];
#pragma unroll
    for (int i = 0; i < 8; ++i) { m1[i] = 3.4028235e38f; m2[i] = 3.4028235e38f; i1[i] = 0; }

    p1_issue_b(sb, 0, tid);
    p1_issue_b(sb, 1, tid);

    const int NITER = 32 * 4;
    int tile = 0, c = 0;
    for (int g = 0; g < NITER; ++g) {
        __syncthreads();
        if (g + 2 < NITER) {
            p1_issue_b(sb, g + 2, tid);
            asm volatile("cp.async.wait_group 2;" ::: "memory");
        } else if (g + 1 < NITER) {
            asm volatile("cp.async.wait_group 1;" ::: "memory");
        } else {
            asm volatile("cp.async.wait_group 0;" ::: "memory");
        }
        __syncthreads();

        if (c == 0) shn[tid] = d_half_norm[tile * CTAN + tid];

        const uint32_t ab = sb + P1_OFF_A + (uint32_t)c * 16384;
        const uint32_t bb = sb + P1_OFF_B + (uint32_t)(g % 3) * 32768;
#pragma unroll
        for (int s = 0; s < 4; ++s) {
            uint32_t a[4][4];
#pragma unroll
            for (int mi = 0; mi < 4; ++mi) {
                int r = wm * 64 + mi * 16 + (lane & 7) + ((lane >> 3) & 1) * 8;
                int u = s * 2 + (lane >> 4);
                uint32_t off = ((uint32_t)(r >> 3) << 10) + ((uint32_t)(r & 7) << 7)
                             + ((uint32_t)u << 4);
                asm volatile("ldmatrix.sync.aligned.m8n8.x4.shared.b16 {%0,%1,%2,%3}, [%4];"
                    : "=r"(a[mi][0]), "=r"(a[mi][1]), "=r"(a[mi][2]), "=r"(a[mi][3])
                    : "r"(ab + SWZ(off)));
            }
            uint32_t b[8][2];
#pragma unroll
            for (int nq = 0; nq < 4; ++nq) {
                int r = wn * 64 + nq * 16 + (lane & 7) + ((lane >> 4) & 1) * 8;
                int u = s * 2 + ((lane >> 3) & 1);
                uint32_t off = ((uint32_t)(r >> 3) << 10) + ((uint32_t)(r & 7) << 7)
                             + ((uint32_t)u << 4);
                asm volatile("ldmatrix.sync.aligned.m8n8.x4.shared.b16 {%0,%1,%2,%3}, [%4];"
                    : "=r"(b[2*nq][0]), "=r"(b[2*nq][1]), "=r"(b[2*nq+1][0]), "=r"(b[2*nq+1][1])
                    : "r"(bb + SWZ(off)));
            }
#pragma unroll
            for (int mi = 0; mi < 4; ++mi)
#pragma unroll
                for (int ni = 0; ni < 8; ++ni)
                    asm volatile("mma.sync.aligned.m16n8k16.row.col.f32.f16.f16.f32 "
                        "{%0,%1,%2,%3}, {%4,%5,%6,%7}, {%8,%9}, {%0,%1,%2,%3};"
                        : "+f"(acc[mi][ni][0]), "+f"(acc[mi][ni][1]),
                          "+f"(acc[mi][ni][2]), "+f"(acc[mi][ni][3])
                        : "r"(a[mi][0]), "r"(a[mi][1]), "r"(a[mi][2]), "r"(a[mi][3]),
                          "r"(b[ni][0]), "r"(b[ni][1]));
        }

        if (c == 3) {
#pragma unroll
            for (int ni = 0; ni < 8; ++ni)
#pragma unroll
                for (int c2 = 0; c2 < 2; ++c2) {
                    int coll = wn * 64 + ni * 8 + (lane & 3) * 2 + c2;
                    float hv = shn[coll];
                    int gcol = tile * CTAN + coll;
#pragma unroll
                    for (int mi = 0; mi < 4; ++mi)
#pragma unroll
                        for (int h = 0; h < 2; ++h) {
                            float sc = hv - acc[mi][ni][h * 2 + c2];
                            int rm = mi * 2 + h;
                            if (sc < m1[rm]) { m2[rm] = m1[rm]; m1[rm] = sc; i1[rm] = gcol; }
                            else if (sc < m2[rm]) { m2[rm] = sc; }
                            acc[mi][ni][h * 2 + c2] = 0.f;
                        }
                }
            tile++; c = 0;
        } else {
            c++;
        }
    }

    // reduce (m1,i1,m2) per row; scratch aliases B ring
    __syncthreads();
    float* rv = (float*)(smem + P1_OFF_RV);
    int*   ri = (int*)(smem + P1_OFF_RI);
    float* r2 = (float*)(smem + P1_OFF_R2);
#pragma unroll
    for (int rm = 0; rm < 8; ++rm) {
        float v = m1[rm], v2 = m2[rm];
        int ix = i1[rm];
#pragma unroll
        for (int o = 1; o <= 2; o <<= 1) {
            float ov  = __shfl_xor_sync(0xffffffffu, v, o);
            int   oi  = __shfl_xor_sync(0xffffffffu, ix, o);
            float ov2 = __shfl_xor_sync(0xffffffffu, v2, o);
            if (ov < v || (ov == v && oi < ix)) {
                v2 = fminf(v, ov2); v = ov; ix = oi;
            } else {
                v2 = fminf(v2, ov);
            }
        }
        if ((lane & 3) == 0) {
            int ml = wm * 64 + (rm >> 1) * 16 + (rm & 1) * 8 + (lane >> 2);
            rv[ml * 4 + wn] = v; ri[ml * 4 + wn] = ix; r2[ml * 4 + wn] = v2;
        }
    }
    __syncthreads();
    if (tid < 128) {
        float v = rv[tid * 4], v2 = r2[tid * 4];
        int ix = ri[tid * 4];
#pragma unroll
        for (int w = 1; w < 4; ++w) {
            float ov = rv[tid * 4 + w], ov2 = r2[tid * 4 + w];
            int oi = ri[tid * 4 + w];
            if (ov < v || (ov == v && oi < ix)) {
                v2 = fminf(v, ov2); v = ov; ix = oi;
            } else {
                v2 = fminf(v2, ov);
            }
        }
        const int row = m0 + tid;
        d_indices[row] = ix;
        // certified bound: |approx - exact| <= 2^-10 ||x|| ||e||  (x,e fp16 RN)
        float thr = 0.00205f * d_xnorm[row] * __int_as_float(d_emax_bits) + 1e-4f;
        if (!(v2 - v > thr)) {
            int pos = atomicAdd(&d_count, 1);
            d_amb[pos] = row;
        }
    }
}

// ---------------------------------------------------------------------------
// Rescue: exact 3-product GEMM over ambiguous rows, N-split by 4
// ---------------------------------------------------------------------------
__device__ __forceinline__ void rs_issue_b(uint32_t sb, int g2, int ns, int tid) {
    const int t2 = g2 / 12;
    const int c2 = g2 - t2 * 12;
    const int seg = (c2 < 8) ? c2 : (c2 - 8);
    const __half* src = d_B + (size_t)(ns * 2048 + t2 * CTAN) * 512 + seg * 64;
    uint32_t db = sb + RS_OFF_B + (uint32_t)(g2 % 3) * 32768;
#pragma unroll
    for (int j = 0; j < 8; ++j) {
        int i = tid + 256 * j;
        int r = i >> 3, u = i & 7;
        const void* gp = (const void*)(src + (size_t)r * 512 + u * 8);
        uint32_t off = (uint32_t)(((r >> 3) << 10) + ((r & 7) << 7) + (u << 4));
        asm volatile("cp.async.cg.shared.global [%0], [%1], 16;"
                     :: "r"(db + SWZ(off)), "l"(gp));
    }
    asm volatile("cp.async.commit_group;" ::: "memory");
}

__global__ __launch_bounds__(256, 1) void vq_rescue_kernel() {
    const int count = d_count;
    const int mt = blockIdx.x >> 2;
    const int ns = blockIdx.x & 3;
    const int m0 = mt * CTAM;
    if (m0 >= count) return;

    extern __shared__ __align__(1024) char smem[];
    const uint32_t sb = smem_u32(smem);
    const int tid  = threadIdx.x;
    const int lane = tid & 31, wid = tid >> 5;
    const int wm = wid >> 2, wn = wid & 3;
    float* shn = (float*)(smem + RS_OFF_HN);

    // A resident: gather ambiguous rows, both planes
    {
#pragma unroll
        for (int q = 0; q < 32; ++q) {
            int i = tid + 256 * q;            // 0..8191 16B units
            int p = i >> 10;
            int r = (i >> 3) & 127;
            int u = i & 7;
            int slot = m0 + r;
            int row = d_amb[slot < count ? slot : count - 1];
            uint4 v = *(const uint4*)(d_A + (size_t)row * 512 + p * 64 + u * 8);
            uint32_t off = (uint32_t)(p * 16384 + ((r >> 3) << 10) + ((r & 7) << 7) + (u << 4));
            *(uint4*)(smem + RS_OFF_A + SWZ(off)) = v;
        }
    }

    float acc[4][8][4];
#pragma unroll
    for (int mi = 0; mi < 4; ++mi)
#pragma unroll
        for (int ni = 0; ni < 8; ++ni)
#pragma unroll
            for (int k = 0; k < 4; ++k) acc[mi][ni][k] = 0.f;
    float minv[8];
    int   mini[8];
#pragma unroll
    for (int i = 0; i < 8; ++i) { minv[i] = 3.4028235e38f; mini[i] = 0; }

    rs_issue_b(sb, 0, ns, tid);
    rs_issue_b(sb, 1, ns, tid);

    const int NITER = 8 * 12;                 // 8 tiles per split
    int tile = 0, c = 0;
    for (int g = 0; g < NITER; ++g) {
        __syncthreads();
        if (g + 2 < NITER) {
            rs_issue_b(sb, g + 2, ns, tid);
            asm volatile("cp.async.wait_group 2;" ::: "memory");
        } else if (g + 1 < NITER) {
            asm volatile("cp.async.wait_group 1;" ::: "memory");
        } else {
            asm volatile("cp.async.wait_group 0;" ::: "memory");
        }
        __syncthreads();

        if (c == 0) shn[tid] = d_half_norm[ns * 2048 + tile * CTAN + tid];

        const int apl = (c < 8) ? (c & 3) : (c - 4);
        const uint32_t ab = sb + RS_OFF_A + (uint32_t)apl * 16384;
        const uint32_t bb = sb + RS_OFF_B + (uint32_t)(g % 3) * 32768;
#pragma unroll
        for (int s = 0; s < 4; ++s) {
            uint32_t a[4][4];
#pragma unroll
            for (int mi = 0; mi < 4; ++mi) {
                int r = wm * 64 + mi * 16 + (lane & 7) + ((lane >> 3) & 1) * 8;
                int u = s * 2 + (lane >> 4);
                uint32_t off = ((uint32_t)(r >> 3) << 10) + ((uint32_t)(r & 7) << 7)
                             + ((uint32_t)u << 4);
                asm volatile("ldmatrix.sync.aligned.m8n8.x4.shared.b16 {%0,%1,%2,%3}, [%4];"
                    : "=r"(a[mi][0]), "=r"(a[mi][1]), "=r"(a[mi][2]), "=r"(a[mi][3])
                    : "r"(ab + SWZ(off)));
            }
            uint32_t b[8][2];
#pragma unroll
            for (int nq = 0; nq < 4; ++nq) {
                int r = wn * 64 + nq * 16 + (lane & 7) + ((lane >> 4) & 1) * 8;
                int u = s * 2 + ((lane >> 3) & 1);
                uint32_t off = ((uint32_t)(r >> 3) << 10) + ((uint32_t)(r & 7) << 7)
                             + ((uint32_t)u << 4);
                asm volatile("ldmatrix.sync.aligned.m8n8.x4.shared.b16 {%0,%1,%2,%3}, [%4];"
                    : "=r"(b[2*nq][0]), "=r"(b[2*nq][1]), "=r"(b[2*nq+1][0]), "=r"(b[2*nq+1][1])
                    : "r"(bb + SWZ(off)));
            }
#pragma unroll
            for (int mi = 0; mi < 4; ++mi)
#pragma unroll
                for (int ni = 0; ni < 8; ++ni)
                    asm volatile("mma.sync.aligned.m16n8k16.row.col.f32.f16.f16.f32 "
                        "{%0,%1,%2,%3}, {%4,%5,%6,%7}, {%8,%9}, {%0,%1,%2,%3};"
                        : "+f"(acc[mi][ni][0]), "+f"(acc[mi][ni][1]),
                          "+f"(acc[mi][ni][2]), "+f"(acc[mi][ni][3])
                        : "r"(a[mi][0]), "r"(a[mi][1]), "r"(a[mi][2]), "r"(a[mi][3]),
                          "r"(b[ni][0]), "r"(b[ni][1]));
        }

        if (c == 11) {
#pragma unroll
            for (int ni = 0; ni < 8; ++ni)
#pragma unroll
                for (int c2 = 0; c2 < 2; ++c2) {
                    int coll = wn * 64 + ni * 8 + (lane & 3) * 2 + c2;
                    float hv = shn[coll];
                    int gcol = ns * 2048 + tile * CTAN + coll;
#pragma unroll
                    for (int mi = 0; mi < 4; ++mi)
#pragma unroll
                        for (int h = 0; h < 2; ++h) {
                            float sc = hv - acc[mi][ni][h * 2 + c2];
                            int rm = mi * 2 + h;
                            if (sc < minv[rm]) { minv[rm] = sc; mini[rm] = gcol; }
                            acc[mi][ni][h * 2 + c2] = 0.f;
                        }
                }
            tile++; c = 0;
        } else {
            c++;
        }
    }

    __syncthreads();
    float* rv = (float*)(smem + RS_OFF_RV);
    int*   ri = (int*)(smem + RS_OFF_RI);
#pragma unroll
    for (int rm = 0; rm < 8; ++rm) {
        float v = minv[rm]; int ix = mini[rm];
#pragma unroll
        for (int o = 1; o <= 2; o <<= 1) {
            float ov = __shfl_xor_sync(0xffffffffu, v, o);
            int   oi = __shfl_xor_sync(0xffffffffu, ix, o);
            if (ov < v || (ov == v && oi < ix)) { v = ov; ix = oi; }
        }
        if ((lane & 3) == 0) {
            int ml = wm * 64 + (rm >> 1) * 16 + (rm & 1) * 8 + (lane >> 2);
            rv[ml * 4 + wn] = v;
            ri[ml * 4 + wn] = ix;
        }
    }
    __syncthreads();
    if (tid < 128) {
        float v = rv[tid * 4]; int ix = ri[tid * 4];
#pragma unroll
        for (int w = 1; w < 4; ++w) {
            float ov = rv[tid * 4 + w]; int oi = ri[tid * 4 + w];
            if (ov < v || (ov == v && oi < ix)) { v = ov; ix = oi; }
        }
        int slot = m0 + tid;
        if (slot < count) {
            d_resc_v[ns * NN + slot] = v;
            d_resc_i[ns * NN + slot] = ix;
        }
    }
}

__global__ void vq_amb_merge_kernel() {
    int i = blockIdx.x * blockDim.x + threadIdx.x;
    if (i < d_count) {
        float v = d_resc_v[i]; int ix = d_resc_i[i];
#pragma unroll
        for (int s = 1; s < NSPLIT; ++s) {
            float ov = d_resc_v[s * NN + i]; int oi = d_resc_i[s * NN + i];
            if (ov < v || (ov == v && oi < ix)) { v = ov; ix = oi; }
        }
        d_indices[d_amb[i]] = ix;
    }
}

// ---------------------------------------------------------------------------
// gather (+ usage histogram) + stats
// ---------------------------------------------------------------------------
__global__ void vq_gather_kernel(const float* __restrict__ ze,
                                 const float* __restrict__ emb,
                                 float* __restrict__ out) {
    int m = blockIdx.x, t = threadIdx.x;
    int idx = d_indices[m];
    float4 e = *(const float4*)(emb + (size_t)idx * DD + t * 4);
    float4 x = *(const float4*)(ze  + (size_t)m   * DD + t * 4);
    float4 st;
    st.x = x.x + (e.x - x.x); st.y = x.y + (e.y - x.y);
    st.z = x.z + (e.z - x.z); st.w = x.w + (e.w - x.w);
    *(float4*)(out + (size_t)m * DD + t * 4) = st;
    *(float4*)(out + (size_t)NN * DD + (size_t)m * DD + t * 4) = e;
    if (t == 0) {
        out[(size_t)2 * NN * DD + m] = (float)idx;
        atomicAdd(&d_usage[idx], 1);
    }
}

__global__ void vq_stats_kernel(float* __restrict__ out) {
    __shared__ float sH[32];
    __shared__ int   sD[32];
    int t = threadIdx.x;
    float H = 0.f; int dead = 0;
    const float inv_total = 1.0f / (float)NN;
    for (int k = t; k < KK; k += 1024) {
        int u = d_usage[k];
        if (u == 0) dead++;
        else { float p = (float)u * inv_total; H += p * logf(p); }
    }
#pragma unroll
    for (int o = 16; o; o >>= 1) {
        H    += __shfl_xor_sync(0xffffffffu, H, o);
        dead += __shfl_xor_sync(0xffffffffu, dead, o);
    }
    if ((t & 31) == 0) { sH[t >> 5] = H; sD[t >> 5] = dead; }
    __syncthreads();
    if (t == 0) {
        float Ht = 0.f; int dt = 0;
        for (int w = 0; w < 32; w++) { Ht += sH[w]; dt += sD[w]; }
        size_t off = (size_t)2 * NN * DD + NN;
        out[off + 0] = expf(-Ht);
        out[off + 1] = (float)dt / (float)KK;
    }
}

// ---------------------------------------------------------------------------
extern "C" void kernel_launch(void* const* d_in, const int* in_sizes, int n_in,
                              void* d_out, int out_size) {
    const float* ze  = (const float*)d_in[0];
    const float* emb = (const float*)d_in[1];
    float* out = (float*)d_out;

    cudaFuncSetAttribute(vq_pass1_kernel, cudaFuncAttributeMaxDynamicSharedMemorySize,
                         P1_SMEM);
    cudaFuncSetAttribute(vq_rescue_kernel, cudaFuncAttributeMaxDynamicSharedMemorySize,
                         RS_SMEM);

    vq_split_ze<<<NN * 128 / 256, 256>>>(ze);
    vq_split_emb<<<KK * 128 / 256, 256>>>(emb);
    vq_xnorm_kernel<<<NN / 8, 256>>>(ze);
    vq_norms_kernel<<<KK / 8, 256>>>(emb);
    vq_pass1_kernel<<<NN / CTAM, 256, P1_SMEM>>>();
    vq_rescue_kernel<<<(NN / CTAM) * NSPLIT, 256, RS_SMEM>>>();
    vq_amb_merge_kernel<<<NN / 256, 256>>>();
    vq_gather_kernel<<<NN, 64>>>(ze, emb, out);
    vq_stats_kernel<<<1, 1024>>>(out);
}

// round 7
// speedup vs baseline: 4.4448x; 1.0335x over previous
#include <cuda_runtime.h>
#include <cuda_fp16.h>
#include <cstdint>

#define DD   256
#define KK   8192
#define NN   32768
#define CTAM 128
#define CTAN 256
#define NSPLIT 4                  // rescue N-splits (2048 codes each)

// ---- pass1 smem layout (A = a0 only, 4 planes; B stages of 64KB = 2 sub-chunks)
#define P1_OFF_A  0               // 4 x 16384 = 65536
#define P1_OFF_B  65536           // 2 stages x 65536 = 131072
#define P1_OFF_HN 196608          // 256 floats
#define P1_SMEM   197632
#define P1_OFF_RV P1_OFF_B
#define P1_OFF_RI (P1_OFF_B + 2048)
#define P1_OFF_R2 (P1_OFF_B + 4096)

// ---- rescue smem layout (A = [a0|a1], 8 planes; 3-stage 32KB ring)
#define RS_OFF_A  0               // 8 x 16384 = 131072
#define RS_OFF_B  131072          // 3 stages x 32768
#define RS_OFF_HN 229376
#define RS_SMEM   230400
#define RS_OFF_RV RS_OFF_B
#define RS_OFF_RI (RS_OFF_B + 2048)

#define SWZ(x) ((x) ^ (((x) >> 3) & 0x70))

// Scratch (no allocations allowed)
__device__ float d_half_norm[KK];
__device__ float d_xnorm[NN];
__device__ int   d_usage[KK];
__device__ int   d_indices[NN];
__device__ int   d_count;
__device__ int   d_emax_bits;
__device__ int   d_amb[NN];
__device__ float d_resc_v[NSPLIT * NN];
__device__ int   d_resc_i[NSPLIT * NN];
__device__ __half d_A[(size_t)NN * 512];   // [a0(256) | a1(256)] per row
__device__ __half d_B[(size_t)KK * 512];   // [b0(256) | b1(256)] per row

__device__ __forceinline__ uint32_t smem_u32(const void* p) {
    uint32_t a;
    asm("{ .reg .u64 t; cvta.to.shared.u64 t, %1; cvt.u32.u64 %0, t; }" : "=r"(a) : "l"(p));
    return a;
}

// ---------------------------------------------------------------------------
// Fused splits: exact 2-way fp16 split + row norms (warp per row)
// ---------------------------------------------------------------------------
__global__ void vq_split_ze(const float* __restrict__ src) {
    if (blockIdx.x == 0 && threadIdx.x == 0) { d_count = 0; d_emax_bits = 0; }
    int row  = blockIdx.x * 8 + (threadIdx.x >> 5);
    int lane = threadIdx.x & 31;
    const float4* x4 = (const float4*)(src + (size_t)row * DD + lane * 8);
    float4 v0 = x4[0], v1 = x4[1];
    float vv[8] = {v0.x, v0.y, v0.z, v0.w, v1.x, v1.y, v1.z, v1.w};
    __half h0[8], h1[8];
    float s = 0.f;
#pragma unroll
    for (int i = 0; i < 8; ++i) {
        h0[i] = __float2half_rn(vv[i]);
        h1[i] = __float2half_rn(vv[i] - __half2float(h0[i]));
        s += vv[i] * vv[i];
    }
#pragma unroll
    for (int o = 16; o; o >>= 1) s += __shfl_xor_sync(0xffffffffu, s, o);
    if (lane == 0) d_xnorm[row] = sqrtf(s);
    *(uint4*)(d_A + (size_t)row * 512 + lane * 8)       = *(uint4*)h0;
    *(uint4*)(d_A + (size_t)row * 512 + 256 + lane * 8) = *(uint4*)h1;
}
__global__ void vq_split_emb(const float* __restrict__ src) {
    int row  = blockIdx.x * 8 + (threadIdx.x >> 5);
    int lane = threadIdx.x & 31;
    const float4* x4 = (const float4*)(src + (size_t)row * DD + lane * 8);
    float4 v0 = x4[0], v1 = x4[1];
    float vv[8] = {v0.x, v0.y, v0.z, v0.w, v1.x, v1.y, v1.z, v1.w};
    __half h0[8], h1[8];
    float s = 0.f;
#pragma unroll
    for (int i = 0; i < 8; ++i) {
        h0[i] = __float2half_rn(vv[i]);
        h1[i] = __float2half_rn(vv[i] - __half2float(h0[i]));
        s += vv[i] * vv[i];
    }
#pragma unroll
    for (int o = 16; o; o >>= 1) s += __shfl_xor_sync(0xffffffffu, s, o);
    if (lane == 0) {
        d_half_norm[row] = 0.5f * s;
        atomicMax(&d_emax_bits, __float_as_int(sqrtf(s)));
    }
    *(uint4*)(d_B + (size_t)row * 512 + lane * 8)       = *(uint4*)h0;
    *(uint4*)(d_B + (size_t)row * 512 + 256 + lane * 8) = *(uint4*)h1;
    int g = blockIdx.x * blockDim.x + threadIdx.x;
    if (g < KK) d_usage[g] = 0;
}

// ---------------------------------------------------------------------------
// Pass 1: single-product (a0*b0) GEMM + min1/min2 + certification.
// 64 iterations, each = 128 K-halves (2 sub-chunks) per sync pair.
// ---------------------------------------------------------------------------
__device__ __forceinline__ void p1_issue_pair(uint32_t sb, int g2, int tid) {
    const int t2 = g2 >> 1, pair = g2 & 1;
    uint32_t db = sb + P1_OFF_B + (uint32_t)(g2 & 1) * 65536;
#pragma unroll
    for (int sub = 0; sub < 2; ++sub) {
        const int seg = pair * 2 + sub;                 // b0 segs 0-3
        const __half* src = d_B + (size_t)(t2 * CTAN) * 512 + seg * 64;
        uint32_t dsub = db + (uint32_t)sub * 32768;
#pragma unroll
        for (int j = 0; j < 8; ++j) {
            int i = tid + 256 * j;
            int r = i >> 3, u = i & 7;
            const void* gp = (const void*)(src + (size_t)r * 512 + u * 8);
            uint32_t off = (uint32_t)(((r >> 3) << 10) + ((r & 7) << 7) + (u << 4));
            asm volatile("cp.async.cg.shared.global [%0], [%1], 16;"
                         :: "r"(dsub + SWZ(off)), "l"(gp));
        }
    }
    asm volatile("cp.async.commit_group;" ::: "memory");
}

__global__ __launch_bounds__(256, 1) void vq_pass1_kernel() {
    extern __shared__ __align__(1024) char smem[];
    const uint32_t sb = smem_u32(smem);
    const int tid  = threadIdx.x;
    const int lane = tid & 31, wid = tid >> 5;
    const int wm = wid >> 2, wn = wid & 3;
    const int m0 = blockIdx.x * CTAM;
    float* shn = (float*)(smem + P1_OFF_HN);

    // A resident: a0 only, 4 planes
    {
        const __half* Arow = d_A + (size_t)m0 * 512;
#pragma unroll
        for (int q = 0; q < 16; ++q) {
            int i = tid + 256 * q;            // 0..4095 16B units
            int p = i >> 10;
            int r = (i >> 3) & 127;
            int u = i & 7;
            uint4 v = *(const uint4*)(Arow + (size_t)r * 512 + p * 64 + u * 8);
            uint32_t off = (uint32_t)(p * 16384 + ((r >> 3) << 10) + ((r & 7) << 7) + (u << 4));
            *(uint4*)(smem + P1_OFF_A + SWZ(off)) = v;
        }
    }

    float acc[4][8][4];
#pragma unroll
    for (int mi = 0; mi < 4; ++mi)
#pragma unroll
        for (int ni = 0; ni < 8; ++ni)
#pragma unroll
            for (int k = 0; k < 4; ++k) acc[mi][ni][k] = 0.f;
    float m1[8], m2[8];
    int   i1[8];
#pragma unroll
    for (int i = 0; i < 8; ++i) { m1[i] = 3.4028235e38f; m2[i] = 3.4028235e38f; i1[i] = 0; }

    p1_issue_pair(sb, 0, tid);

    const int NITER = 64;                     // 32 tiles x 2 pairs
    for (int g2 = 0; g2 < NITER; ++g2) {
        __syncthreads();
        if (g2 + 1 < NITER) {
            p1_issue_pair(sb, g2 + 1, tid);
            asm volatile("cp.async.wait_group 1;" ::: "memory");
        } else {
            asm volatile("cp.async.wait_group 0;" ::: "memory");
        }
        __syncthreads();

        const int tile = g2 >> 1, pair = g2 & 1;
        if (pair == 0) shn[tid] = d_half_norm[tile * CTAN + tid];

#pragma unroll
        for (int sub = 0; sub < 2; ++sub) {
            const int c = pair * 2 + sub;
            const uint32_t ab = sb + P1_OFF_A + (uint32_t)c * 16384;
            const uint32_t bb = sb + P1_OFF_B + (uint32_t)(g2 & 1) * 65536
                              + (uint32_t)sub * 32768;
#pragma unroll
            for (int s = 0; s < 4; ++s) {
                uint32_t a[4][4];
#pragma unroll
                for (int mi = 0; mi < 4; ++mi) {
                    int r = wm * 64 + mi * 16 + (lane & 7) + ((lane >> 3) & 1) * 8;
                    int u = s * 2 + (lane >> 4);
                    uint32_t off = ((uint32_t)(r >> 3) << 10) + ((uint32_t)(r & 7) << 7)
                                 + ((uint32_t)u << 4);
                    asm volatile("ldmatrix.sync.aligned.m8n8.x4.shared.b16 {%0,%1,%2,%3}, [%4];"
                        : "=r"(a[mi][0]), "=r"(a[mi][1]), "=r"(a[mi][2]), "=r"(a[mi][3])
                        : "r"(ab + SWZ(off)));
                }
                uint32_t b[8][2];
#pragma unroll
                for (int nq = 0; nq < 4; ++nq) {
                    int r = wn * 64 + nq * 16 + (lane & 7) + ((lane >> 4) & 1) * 8;
                    int u = s * 2 + ((lane >> 3) & 1);
                    uint32_t off = ((uint32_t)(r >> 3) << 10) + ((uint32_t)(r & 7) << 7)
                                 + ((uint32_t)u << 4);
                    asm volatile("ldmatrix.sync.aligned.m8n8.x4.shared.b16 {%0,%1,%2,%3}, [%4];"
                        : "=r"(b[2*nq][0]), "=r"(b[2*nq][1]), "=r"(b[2*nq+1][0]), "=r"(b[2*nq+1][1])
                        : "r"(bb + SWZ(off)));
                }
#pragma unroll
                for (int mi = 0; mi < 4; ++mi)
#pragma unroll
                    for (int ni = 0; ni < 8; ++ni)
                        asm volatile("mma.sync.aligned.m16n8k16.row.col.f32.f16.f16.f32 "
                            "{%0,%1,%2,%3}, {%4,%5,%6,%7}, {%8,%9}, {%0,%1,%2,%3};"
                            : "+f"(acc[mi][ni][0]), "+f"(acc[mi][ni][1]),
                              "+f"(acc[mi][ni][2]), "+f"(acc[mi][ni][3])
                            : "r"(a[mi][0]), "r"(a[mi][1]), "r"(a[mi][2]), "r"(a[mi][3]),
                              "r"(b[ni][0]), "r"(b[ni][1]));
            }

            if (c == 3) {
#pragma unroll
                for (int ni = 0; ni < 8; ++ni)
#pragma unroll
                    for (int c2 = 0; c2 < 2; ++c2) {
                        int coll = wn * 64 + ni * 8 + (lane & 3) * 2 + c2;
                        float hv = shn[coll];
                        int gcol = tile * CTAN + coll;
#pragma unroll
                        for (int mi = 0; mi < 4; ++mi)
#pragma unroll
                            for (int h = 0; h < 2; ++h) {
                                float sc = hv - acc[mi][ni][h * 2 + c2];
                                int rm = mi * 2 + h;
                                if (sc < m1[rm]) { m2[rm] = m1[rm]; m1[rm] = sc; i1[rm] = gcol; }
                                else if (sc < m2[rm]) { m2[rm] = sc; }
                                acc[mi][ni][h * 2 + c2] = 0.f;
                            }
                    }
            }
        }
    }

    // reduce (m1,i1,m2) per row; scratch aliases B ring
    __syncthreads();
    float* rv = (float*)(smem + P1_OFF_RV);
    int*   ri = (int*)(smem + P1_OFF_RI);
    float* r2 = (float*)(smem + P1_OFF_R2);
#pragma unroll
    for (int rm = 0; rm < 8; ++rm) {
        float v = m1[rm], v2 = m2[rm];
        int ix = i1[rm];
#pragma unroll
        for (int o = 1; o <= 2; o <<= 1) {
            float ov  = __shfl_xor_sync(0xffffffffu, v, o);
            int   oi  = __shfl_xor_sync(0xffffffffu, ix, o);
            float ov2 = __shfl_xor_sync(0xffffffffu, v2, o);
            if (ov < v || (ov == v && oi < ix)) {
                v2 = fminf(v, ov2); v = ov; ix = oi;
            } else {
                v2 = fminf(v2, ov);
            }
        }
        if ((lane & 3) == 0) {
            int ml = wm * 64 + (rm >> 1) * 16 + (rm & 1) * 8 + (lane >> 2);
            rv[ml * 4 + wn] = v; ri[ml * 4 + wn] = ix; r2[ml * 4 + wn] = v2;
        }
    }
    __syncthreads();
    if (tid < 128) {
        float v = rv[tid * 4], v2 = r2[tid * 4];
        int ix = ri[tid * 4];
#pragma unroll
        for (int w = 1; w < 4; ++w) {
            float ov = rv[tid * 4 + w], ov2 = r2[tid * 4 + w];
            int oi = ri[tid * 4 + w];
            if (ov < v || (ov == v && oi < ix)) {
                v2 = fminf(v, ov2); v = ov; ix = oi;
            } else {
                v2 = fminf(v2, ov);
            }
        }
        const int row = m0 + tid;
        d_indices[row] = ix;
        // certified: |approx - exact| <= 2^-10 ||x|| ||e||  (fp16 RN operands)
        float thr = 0.00205f * d_xnorm[row] * __int_as_float(d_emax_bits) + 1e-4f;
        if (!(v2 - v > thr)) {
            int pos = atomicAdd(&d_count, 1);
            d_amb[pos] = row;
        }
    }
}

// ---------------------------------------------------------------------------
// Rescue: exact 3-product GEMM over ambiguous rows, N-split by 4
// ---------------------------------------------------------------------------
__device__ __forceinline__ void rs_issue_b(uint32_t sb, int g2, int ns, int tid) {
    const int t2 = g2 / 12;
    const int c2 = g2 - t2 * 12;
    const int seg = (c2 < 8) ? c2 : (c2 - 8);
    const __half* src = d_B + (size_t)(ns * 2048 + t2 * CTAN) * 512 + seg * 64;
    uint32_t db = sb + RS_OFF_B + (uint32_t)(g2 % 3) * 32768;
#pragma unroll
    for (int j = 0; j < 8; ++j) {
        int i = tid + 256 * j;
        int r = i >> 3, u = i & 7;
        const void* gp = (const void*)(src + (size_t)r * 512 + u * 8);
        uint32_t off = (uint32_t)(((r >> 3) << 10) + ((r & 7) << 7) + (u << 4));
        asm volatile("cp.async.cg.shared.global [%0], [%1], 16;"
                     :: "r"(db + SWZ(off)), "l"(gp));
    }
    asm volatile("cp.async.commit_group;" ::: "memory");
}

__global__ __launch_bounds__(256, 1) void vq_rescue_kernel() {
    const int count = d_count;
    const int mt = blockIdx.x >> 2;
    const int ns = blockIdx.x & 3;
    const int m0 = mt * CTAM;
    if (m0 >= count) return;

    extern __shared__ __align__(1024) char smem[];
    const uint32_t sb = smem_u32(smem);
    const int tid  = threadIdx.x;
    const int lane = tid & 31, wid = tid >> 5;
    const int wm = wid >> 2, wn = wid & 3;
    float* shn = (float*)(smem + RS_OFF_HN);

    // A resident: gather ambiguous rows, both planes
    {
#pragma unroll
        for (int q = 0; q < 32; ++q) {
            int i = tid + 256 * q;            // 0..8191 16B units
            int p = i >> 10;
            int r = (i >> 3) & 127;
            int u = i & 7;
            int slot = m0 + r;
            int row = d_amb[slot < count ? slot : count - 1];
            uint4 v = *(const uint4*)(d_A + (size_t)row * 512 + p * 64 + u * 8);
            uint32_t off = (uint32_t)(p * 16384 + ((r >> 3) << 10) + ((r & 7) << 7) + (u << 4));
            *(uint4*)(smem + RS_OFF_A + SWZ(off)) = v;
        }
    }

    float acc[4][8][4];
#pragma unroll
    for (int mi = 0; mi < 4; ++mi)
#pragma unroll
        for (int ni = 0; ni < 8; ++ni)
#pragma unroll
            for (int k = 0; k < 4; ++k) acc[mi][ni][k] = 0.f;
    float minv[8];
    int   mini[8];
#pragma unroll
    for (int i = 0; i < 8; ++i) { minv[i] = 3.4028235e38f; mini[i] = 0; }

    rs_issue_b(sb, 0, ns, tid);
    rs_issue_b(sb, 1, ns, tid);

    const int NITER = 8 * 12;                 // 8 tiles per split
    int tile = 0, c = 0;
    for (int g = 0; g < NITER; ++g) {
        __syncthreads();
        if (g + 2 < NITER) {
            rs_issue_b(sb, g + 2, ns, tid);
            asm volatile("cp.async.wait_group 2;" ::: "memory");
        } else if (g + 1 < NITER) {
            asm volatile("cp.async.wait_group 1;" ::: "memory");
        } else {
            asm volatile("cp.async.wait_group 0;" ::: "memory");
        }
        __syncthreads();

        if (c == 0) shn[tid] = d_half_norm[ns * 2048 + tile * CTAN + tid];

        const int apl = (c < 8) ? (c & 3) : (c - 4);
        const uint32_t ab = sb + RS_OFF_A + (uint32_t)apl * 16384;
        const uint32_t bb = sb + RS_OFF_B + (uint32_t)(g % 3) * 32768;
#pragma unroll
        for (int s = 0; s < 4; ++s) {
            uint32_t a[4][4];
#pragma unroll
            for (int mi = 0; mi < 4; ++mi) {
                int r = wm * 64 + mi * 16 + (lane & 7) + ((lane >> 3) & 1) * 8;
                int u = s * 2 + (lane >> 4);
                uint32_t off = ((uint32_t)(r >> 3) << 10) + ((uint32_t)(r & 7) << 7)
                             + ((uint32_t)u << 4);
                asm volatile("ldmatrix.sync.aligned.m8n8.x4.shared.b16 {%0,%1,%2,%3}, [%4];"
                    : "=r"(a[mi][0]), "=r"(a[mi][1]), "=r"(a[mi][2]), "=r"(a[mi][3])
                    : "r"(ab + SWZ(off)));
            }
            uint32_t b[8][2];
#pragma unroll
            for (int nq = 0; nq < 4; ++nq) {
                int r = wn * 64 + nq * 16 + (lane & 7) + ((lane >> 4) & 1) * 8;
                int u = s * 2 + ((lane >> 3) & 1);
                uint32_t off = ((uint32_t)(r >> 3) << 10) + ((uint32_t)(r & 7) << 7)
                             + ((uint32_t)u << 4);
                asm volatile("ldmatrix.sync.aligned.m8n8.x4.shared.b16 {%0,%1,%2,%3}, [%4];"
                    : "=r"(b[2*nq][0]), "=r"(b[2*nq][1]), "=r"(b[2*nq+1][0]), "=r"(b[2*nq+1][1])
                    : "r"(bb + SWZ(off)));
            }
#pragma unroll
            for (int mi = 0; mi < 4; ++mi)
#pragma unroll
                for (int ni = 0; ni < 8; ++ni)
                    asm volatile("mma.sync.aligned.m16n8k16.row.col.f32.f16.f16.f32 "
                        "{%0,%1,%2,%3}, {%4,%5,%6,%7}, {%8,%9}, {%0,%1,%2,%3};"
                        : "+f"(acc[mi][ni][0]), "+f"(acc[mi][ni][1]),
                          "+f"(acc[mi][ni][2]), "+f"(acc[mi][ni][3])
                        : "r"(a[mi][0]), "r"(a[mi][1]), "r"(a[mi][2]), "r"(a[mi][3]),
                          "r"(b[ni][0]), "r"(b[ni][1]));
        }

        if (c == 11) {
#pragma unroll
            for (int ni = 0; ni < 8; ++ni)
#pragma unroll
                for (int c2 = 0; c2 < 2; ++c2) {
                    int coll = wn * 64 + ni * 8 + (lane & 3) * 2 + c2;
                    float hv = shn[coll];
                    int gcol = ns * 2048 + tile * CTAN + coll;
#pragma unroll
                    for (int mi = 0; mi < 4; ++mi)
#pragma unroll
                        for (int h = 0; h < 2; ++h) {
                            float sc = hv - acc[mi][ni][h * 2 + c2];
                            int rm = mi * 2 + h;
                            if (sc < minv[rm]) { minv[rm] = sc; mini[rm] = gcol; }
                            acc[mi][ni][h * 2 + c2] = 0.f;
                        }
                }
            tile++; c = 0;
        } else {
            c++;
        }
    }

    __syncthreads();
    float* rv = (float*)(smem + RS_OFF_RV);
    int*   ri = (int*)(smem + RS_OFF_RI);
#pragma unroll
    for (int rm = 0; rm < 8; ++rm) {
        float v = minv[rm]; int ix = mini[rm];
#pragma unroll
        for (int o = 1; o <= 2; o <<= 1) {
            float ov = __shfl_xor_sync(0xffffffffu, v, o);
            int   oi = __shfl_xor_sync(0xffffffffu, ix, o);
            if (ov < v || (ov == v && oi < ix)) { v = ov; ix = oi; }
        }
        if ((lane & 3) == 0) {
            int ml = wm * 64 + (rm >> 1) * 16 + (rm & 1) * 8 + (lane >> 2);
            rv[ml * 4 + wn] = v;
            ri[ml * 4 + wn] = ix;
        }
    }
    __syncthreads();
    if (tid < 128) {
        float v = rv[tid * 4]; int ix = ri[tid * 4];
#pragma unroll
        for (int w = 1; w < 4; ++w) {
            float ov = rv[tid * 4 + w]; int oi = ri[tid * 4 + w];
            if (ov < v || (ov == v && oi < ix)) { v = ov; ix = oi; }
        }
        int slot = m0 + tid;
        if (slot < count) {
            d_resc_v[ns * NN + slot] = v;
            d_resc_i[ns * NN + slot] = ix;
        }
    }
}

__global__ void vq_amb_merge_kernel() {
    int i = blockIdx.x * blockDim.x + threadIdx.x;
    if (i < d_count) {
        float v = d_resc_v[i]; int ix = d_resc_i[i];
#pragma unroll
        for (int s = 1; s < NSPLIT; ++s) {
            float ov = d_resc_v[s * NN + i]; int oi = d_resc_i[s * NN + i];
            if (ov < v || (ov == v && oi < ix)) { v = ov; ix = oi; }
        }
        d_indices[d_amb[i]] = ix;
    }
}

// ---------------------------------------------------------------------------
// gather (+ usage histogram) + stats
// ---------------------------------------------------------------------------
__global__ void vq_gather_kernel(const float* __restrict__ ze,
                                 const float* __restrict__ emb,
                                 float* __restrict__ out) {
    int m = blockIdx.x, t = threadIdx.x;
    int idx = d_indices[m];
    float4 e = *(const float4*)(emb + (size_t)idx * DD + t * 4);
    float4 x = *(const float4*)(ze  + (size_t)m   * DD + t * 4);
    float4 st;
    st.x = x.x + (e.x - x.x); st.y = x.y + (e.y - x.y);
    st.z = x.z + (e.z - x.z); st.w = x.w + (e.w - x.w);
    *(float4*)(out + (size_t)m * DD + t * 4) = st;
    *(float4*)(out + (size_t)NN * DD + (size_t)m * DD + t * 4) = e;
    if (t == 0) {
        out[(size_t)2 * NN * DD + m] = (float)idx;
        atomicAdd(&d_usage[idx], 1);
    }
}

__global__ void vq_stats_kernel(float* __restrict__ out) {
    __shared__ float sH[32];
    __shared__ int   sD[32];
    int t = threadIdx.x;
    float H = 0.f; int dead = 0;
    const float inv_total = 1.0f / (float)NN;
    for (int k = t; k < KK; k += 1024) {
        int u = d_usage[k];
        if (u == 0) dead++;
        else { float p = (float)u * inv_total; H += p * logf(p); }
    }
#pragma unroll
    for (int o = 16; o; o >>= 1) {
        H    += __shfl_xor_sync(0xffffffffu, H, o);
        dead += __shfl_xor_sync(0xffffffffu, dead, o);
    }
    if ((t & 31) == 0) { sH[t >> 5] = H; sD[t >> 5] = dead; }
    __syncthreads();
    if (t == 0) {
        float Ht = 0.f; int dt = 0;
        for (int w = 0; w < 32; w++) { Ht += sH[w]; dt += sD[w]; }
        size_t off = (size_t)2 * NN * DD + NN;
        out[off + 0] = expf(-Ht);
        out[off + 1] = (float)dt / (float)KK;
    }
}

// ---------------------------------------------------------------------------
extern "C" void kernel_launch(void* const* d_in, const int* in_sizes, int n_in,
                              void* d_out, int out_size) {
    const float* ze  = (const float*)d_in[0];
    const float* emb = (const float*)d_in[1];
    float* out = (float*)d_out;

    cudaFuncSetAttribute(vq_pass1_kernel, cudaFuncAttributeMaxDynamicSharedMemorySize,
                         P1_SMEM);
    cudaFuncSetAttribute(vq_rescue_kernel, cudaFuncAttributeMaxDynamicSharedMemorySize,
                         RS_SMEM);

    vq_split_ze<<<NN / 8, 256>>>(ze);
    vq_split_emb<<<KK / 8, 256>>>(emb);
    vq_pass1_kernel<<<NN / CTAM, 256, P1_SMEM>>>();
    vq_rescue_kernel<<<(NN / CTAM) * NSPLIT, 256, RS_SMEM>>>();
    vq_amb_merge_kernel<<<NN / 256, 256>>>();
    vq_gather_kernel<<<NN, 64>>>(ze, emb, out);
    vq_stats_kernel<<<1, 1024>>>(out);
}

// round 8
// speedup vs baseline: 5.1134x; 1.1504x over previous
#include <cuda_runtime.h>
#include <cuda_fp16.h>
#include <cstdint>

#define DD   256
#define KK   8192
#define NN   32768
#define CTAM 128
#define CTAN 256
#define NSPLIT 16                 // rescue N-splits (512 codes each)

// ---- pass1 smem layout (A = a0 only, 4 planes; B stages of 64KB = 2 sub-chunks)
#define P1_OFF_A  0               // 4 x 16384 = 65536
#define P1_OFF_B  65536           // 2 stages x 65536 = 131072
#define P1_OFF_HN 196608          // 256 floats
#define P1_SMEM   197632
#define P1_OFF_RV P1_OFF_B
#define P1_OFF_RI (P1_OFF_B + 2048)
#define P1_OFF_R2 (P1_OFF_B + 4096)

// ---- rescue smem layout (A = [a0|a1], 8 planes; 3-stage 32KB ring)
#define RS_OFF_A  0               // 8 x 16384 = 131072
#define RS_OFF_B  131072          // 3 stages x 32768
#define RS_OFF_HN 229376
#define RS_SMEM   230400
#define RS_OFF_RV RS_OFF_B
#define RS_OFF_RI (RS_OFF_B + 2048)

#define SWZ(x) ((x) ^ (((x) >> 3) & 0x70))

// Scratch (no allocations allowed)
__device__ float d_half_norm[KK];
__device__ float d_a0norm[NN];
__device__ float d_rxnorm[NN];
__device__ int   d_usage[KK];
__device__ int   d_indices[NN];
__device__ int   d_count;
__device__ int   d_b0max_bits;
__device__ int   d_remax_bits;
__device__ int   d_amb[NN];
__device__ float d_resc_v[NSPLIT * NN];
__device__ int   d_resc_i[NSPLIT * NN];
__device__ __half d_A[(size_t)NN * 512];   // [a0(256) | a1(256)] per row
__device__ __half d_B[(size_t)KK * 512];   // [b0(256) | b1(256)] per row

__device__ __forceinline__ uint32_t smem_u32(const void* p) {
    uint32_t a;
    asm("{ .reg .u64 t; cvta.to.shared.u64 t, %1; cvt.u32.u64 %0, t; }" : "=r"(a) : "l"(p));
    return a;
}

// ---------------------------------------------------------------------------
// Fused splits: exact 2-way fp16 split + exact split-part norms (warp per row)
// ---------------------------------------------------------------------------
__global__ void vq_split_ze(const float* __restrict__ src) {
    if (blockIdx.x == 0 && threadIdx.x == 0) {
        d_count = 0; d_b0max_bits = 0; d_remax_bits = 0;
    }
    int row  = blockIdx.x * 8 + (threadIdx.x >> 5);
    int lane = threadIdx.x & 31;
    const float4* x4 = (const float4*)(src + (size_t)row * DD + lane * 8);
    float4 v0 = x4[0], v1 = x4[1];
    float vv[8] = {v0.x, v0.y, v0.z, v0.w, v1.x, v1.y, v1.z, v1.w};
    __half h0[8], h1[8];
    float s0 = 0.f, s1 = 0.f;
#pragma unroll
    for (int i = 0; i < 8; ++i) {
        h0[i] = __float2half_rn(vv[i]);
        float f0 = __half2float(h0[i]);
        h1[i] = __float2half_rn(vv[i] - f0);
        float f1 = __half2float(h1[i]);
        s0 += f0 * f0;
        s1 += f1 * f1;
    }
#pragma unroll
    for (int o = 16; o; o >>= 1) {
        s0 += __shfl_xor_sync(0xffffffffu, s0, o);
        s1 += __shfl_xor_sync(0xffffffffu, s1, o);
    }
    if (lane == 0) { d_a0norm[row] = sqrtf(s0); d_rxnorm[row] = sqrtf(s1); }
    *(uint4*)(d_A + (size_t)row * 512 + lane * 8)       = *(uint4*)h0;
    *(uint4*)(d_A + (size_t)row * 512 + 256 + lane * 8) = *(uint4*)h1;
}
__global__ void vq_split_emb(const float* __restrict__ src) {
    int row  = blockIdx.x * 8 + (threadIdx.x >> 5);
    int lane = threadIdx.x & 31;
    const float4* x4 = (const float4*)(src + (size_t)row * DD + lane * 8);
    float4 v0 = x4[0], v1 = x4[1];
    float vv[8] = {v0.x, v0.y, v0.z, v0.w, v1.x, v1.y, v1.z, v1.w};
    __half h0[8], h1[8];
    float s = 0.f, s0 = 0.f, s1 = 0.f;
#pragma unroll
    for (int i = 0; i < 8; ++i) {
        h0[i] = __float2half_rn(vv[i]);
        float f0 = __half2float(h0[i]);
        h1[i] = __float2half_rn(vv[i] - f0);
        float f1 = __half2float(h1[i]);
        s  += vv[i] * vv[i];
        s0 += f0 * f0;
        s1 += f1 * f1;
    }
#pragma unroll
    for (int o = 16; o; o >>= 1) {
        s  += __shfl_xor_sync(0xffffffffu, s, o);
        s0 += __shfl_xor_sync(0xffffffffu, s0, o);
        s1 += __shfl_xor_sync(0xffffffffu, s1, o);
    }
    if (lane == 0) {
        d_half_norm[row] = 0.5f * s;
        atomicMax(&d_b0max_bits, __float_as_int(sqrtf(s0)));
        atomicMax(&d_remax_bits, __float_as_int(sqrtf(s1)));
    }
    *(uint4*)(d_B + (size_t)row * 512 + lane * 8)       = *(uint4*)h0;
    *(uint4*)(d_B + (size_t)row * 512 + 256 + lane * 8) = *(uint4*)h1;
    int g = blockIdx.x * blockDim.x + threadIdx.x;
    if (g < KK) d_usage[g] = 0;
}

// ---------------------------------------------------------------------------
// Pass 1: single-product (a0*b0) GEMM + min1/min2 + certification.
// ---------------------------------------------------------------------------
__device__ __forceinline__ void p1_issue_pair(uint32_t sb, int g2, int tid) {
    const int t2 = g2 >> 1, pair = g2 & 1;
    uint32_t db = sb + P1_OFF_B + (uint32_t)(g2 & 1) * 65536;
#pragma unroll
    for (int sub = 0; sub < 2; ++sub) {
        const int seg = pair * 2 + sub;                 // b0 segs 0-3
        const __half* src = d_B + (size_t)(t2 * CTAN) * 512 + seg * 64;
        uint32_t dsub = db + (uint32_t)sub * 32768;
#pragma unroll
        for (int j = 0; j < 8; ++j) {
            int i = tid + 256 * j;
            int r = i >> 3, u = i & 7;
            const void* gp = (const void*)(src + (size_t)r * 512 + u * 8);
            uint32_t off = (uint32_t)(((r >> 3) << 10) + ((r & 7) << 7) + (u << 4));
            asm volatile("cp.async.cg.shared.global [%0], [%1], 16;"
                         :: "r"(dsub + SWZ(off)), "l"(gp));
        }
    }
    asm volatile("cp.async.commit_group;" ::: "memory");
}

__global__ __launch_bounds__(256, 1) void vq_pass1_kernel() {
    extern __shared__ __align__(1024) char smem[];
    const uint32_t sb = smem_u32(smem);
    const int tid  = threadIdx.x;
    const int lane = tid & 31, wid = tid >> 5;
    const int wm = wid >> 2, wn = wid & 3;
    const int m0 = blockIdx.x * CTAM;
    float* shn = (float*)(smem + P1_OFF_HN);

    // A resident: a0 only, 4 planes
    {
        const __half* Arow = d_A + (size_t)m0 * 512;
#pragma unroll
        for (int q = 0; q < 16; ++q) {
            int i = tid + 256 * q;            // 0..4095 16B units
            int p = i >> 10;
            int r = (i >> 3) & 127;
            int u = i & 7;
            uint4 v = *(const uint4*)(Arow + (size_t)r * 512 + p * 64 + u * 8);
            uint32_t off = (uint32_t)(p * 16384 + ((r >> 3) << 10) + ((r & 7) << 7) + (u << 4));
            *(uint4*)(smem + P1_OFF_A + SWZ(off)) = v;
        }
    }

    float acc[4][8][4];
#pragma unroll
    for (int mi = 0; mi < 4; ++mi)
#pragma unroll
        for (int ni = 0; ni < 8; ++ni)
#pragma unroll
            for (int k = 0; k < 4; ++k) acc[mi][ni][k] = 0.f;
    float m1[8], m2[8];
    int   i1[8];
#pragma unroll
    for (int i = 0; i < 8; ++i) { m1[i] = 3.4028235e38f; m2[i] = 3.4028235e38f; i1[i] = 0; }

    p1_issue_pair(sb, 0, tid);

    const int NITER = 64;                     // 32 tiles x 2 pairs
    for (int g2 = 0; g2 < NITER; ++g2) {
        __syncthreads();
        if (g2 + 1 < NITER) {
            p1_issue_pair(sb, g2 + 1, tid);
            asm volatile("cp.async.wait_group 1;" ::: "memory");
        } else {
            asm volatile("cp.async.wait_group 0;" ::: "memory");
        }
        __syncthreads();

        const int tile = g2 >> 1, pair = g2 & 1;
        if (pair == 0) shn[tid] = d_half_norm[tile * CTAN + tid];

#pragma unroll
        for (int sub = 0; sub < 2; ++sub) {
            const int c = pair * 2 + sub;
            const uint32_t ab = sb + P1_OFF_A + (uint32_t)c * 16384;
            const uint32_t bb = sb + P1_OFF_B + (uint32_t)(g2 & 1) * 65536
                              + (uint32_t)sub * 32768;
#pragma unroll
            for (int s = 0; s < 4; ++s) {
                uint32_t a[4][4];
#pragma unroll
                for (int mi = 0; mi < 4; ++mi) {
                    int r = wm * 64 + mi * 16 + (lane & 7) + ((lane >> 3) & 1) * 8;
                    int u = s * 2 + (lane >> 4);
                    uint32_t off = ((uint32_t)(r >> 3) << 10) + ((uint32_t)(r & 7) << 7)
                                 + ((uint32_t)u << 4);
                    asm volatile("ldmatrix.sync.aligned.m8n8.x4.shared.b16 {%0,%1,%2,%3}, [%4];"
                        : "=r"(a[mi][0]), "=r"(a[mi][1]), "=r"(a[mi][2]), "=r"(a[mi][3])
                        : "r"(ab + SWZ(off)));
                }
                uint32_t b[8][2];
#pragma unroll
                for (int nq = 0; nq < 4; ++nq) {
                    int r = wn * 64 + nq * 16 + (lane & 7) + ((lane >> 4) & 1) * 8;
                    int u = s * 2 + ((lane >> 3) & 1);
                    uint32_t off = ((uint32_t)(r >> 3) << 10) + ((uint32_t)(r & 7) << 7)
                                 + ((uint32_t)u << 4);
                    asm volatile("ldmatrix.sync.aligned.m8n8.x4.shared.b16 {%0,%1,%2,%3}, [%4];"
                        : "=r"(b[2*nq][0]), "=r"(b[2*nq][1]), "=r"(b[2*nq+1][0]), "=r"(b[2*nq+1][1])
                        : "r"(bb + SWZ(off)));
                }
#pragma unroll
                for (int mi = 0; mi < 4; ++mi)
#pragma unroll
                    for (int ni = 0; ni < 8; ++ni)
                        asm volatile("mma.sync.aligned.m16n8k16.row.col.f32.f16.f16.f32 "
                            "{%0,%1,%2,%3}, {%4,%5,%6,%7}, {%8,%9}, {%0,%1,%2,%3};"
                            : "+f"(acc[mi][ni][0]), "+f"(acc[mi][ni][1]),
                              "+f"(acc[mi][ni][2]), "+f"(acc[mi][ni][3])
                            : "r"(a[mi][0]), "r"(a[mi][1]), "r"(a[mi][2]), "r"(a[mi][3]),
                              "r"(b[ni][0]), "r"(b[ni][1]));
            }

            if (c == 3) {
#pragma unroll
                for (int ni = 0; ni < 8; ++ni)
#pragma unroll
                    for (int c2 = 0; c2 < 2; ++c2) {
                        int coll = wn * 64 + ni * 8 + (lane & 3) * 2 + c2;
                        float hv = shn[coll];
                        int gcol = tile * CTAN + coll;
#pragma unroll
                        for (int mi = 0; mi < 4; ++mi)
#pragma unroll
                            for (int h = 0; h < 2; ++h) {
                                float sc = hv - acc[mi][ni][h * 2 + c2];
                                int rm = mi * 2 + h;
                                if (sc < m1[rm]) { m2[rm] = m1[rm]; m1[rm] = sc; i1[rm] = gcol; }
                                else if (sc < m2[rm]) { m2[rm] = sc; }
                                acc[mi][ni][h * 2 + c2] = 0.f;
                            }
                    }
            }
        }
    }

    // reduce (m1,i1,m2) per row; scratch aliases B ring
    __syncthreads();
    float* rv = (float*)(smem + P1_OFF_RV);
    int*   ri = (int*)(smem + P1_OFF_RI);
    float* r2 = (float*)(smem + P1_OFF_R2);
#pragma unroll
    for (int rm = 0; rm < 8; ++rm) {
        float v = m1[rm], v2 = m2[rm];
        int ix = i1[rm];
#pragma unroll
        for (int o = 1; o <= 2; o <<= 1) {
            float ov  = __shfl_xor_sync(0xffffffffu, v, o);
            int   oi  = __shfl_xor_sync(0xffffffffu, ix, o);
            float ov2 = __shfl_xor_sync(0xffffffffu, v2, o);
            if (ov < v || (ov == v && oi < ix)) {
                v2 = fminf(v, ov2); v = ov; ix = oi;
            } else {
                v2 = fminf(v2, ov);
            }
        }
        if ((lane & 3) == 0) {
            int ml = wm * 64 + (rm >> 1) * 16 + (rm & 1) * 8 + (lane >> 2);
            rv[ml * 4 + wn] = v; ri[ml * 4 + wn] = ix; r2[ml * 4 + wn] = v2;
        }
    }
    __syncthreads();
    if (tid < 128) {
        float v = rv[tid * 4], v2 = r2[tid * 4];
        int ix = ri[tid * 4];
#pragma unroll
        for (int w = 1; w < 4; ++w) {
            float ov = rv[tid * 4 + w], ov2 = r2[tid * 4 + w];
            int oi = ri[tid * 4 + w];
            if (ov < v || (ov == v && oi < ix)) {
                v2 = fminf(v, ov2); v = ov; ix = oi;
            } else {
                v2 = fminf(v2, ov);
            }
        }
        const int row = m0 + tid;
        d_indices[row] = ix;
        // certified Cauchy-Schwarz bound with exact split-part norms:
        // |score_p1 - score_rescue| <= ||a0||*max||b1|| + ||a1||*max||b0||
        float thr = (d_a0norm[row] * __int_as_float(d_remax_bits)
                   + d_rxnorm[row] * __int_as_float(d_b0max_bits)) * 1.01f + 1e-4f;
        if (!(v2 - v > thr)) {
            int pos = atomicAdd(&d_count, 1);
            d_amb[pos] = row;
        }
    }
}

// ---------------------------------------------------------------------------
// Rescue: exact 3-product GEMM over ambiguous rows, N-split by 16 (512 codes)
// ---------------------------------------------------------------------------
__device__ __forceinline__ void rs_issue_b(uint32_t sb, int g2, int ns, int tid) {
    const int t2 = g2 / 12;
    const int c2 = g2 - t2 * 12;
    const int seg = (c2 < 8) ? c2 : (c2 - 8);
    const __half* src = d_B + (size_t)(ns * 512 + t2 * CTAN) * 512 + seg * 64;
    uint32_t db = sb + RS_OFF_B + (uint32_t)(g2 % 3) * 32768;
#pragma unroll
    for (int j = 0; j < 8; ++j) {
        int i = tid + 256 * j;
        int r = i >> 3, u = i & 7;
        const void* gp = (const void*)(src + (size_t)r * 512 + u * 8);
        uint32_t off = (uint32_t)(((r >> 3) << 10) + ((r & 7) << 7) + (u << 4));
        asm volatile("cp.async.cg.shared.global [%0], [%1], 16;"
                     :: "r"(db + SWZ(off)), "l"(gp));
    }
    asm volatile("cp.async.commit_group;" ::: "memory");
}

__global__ __launch_bounds__(256, 1) void vq_rescue_kernel() {
    const int count = d_count;
    const int mt = blockIdx.x >> 4;
    const int ns = blockIdx.x & 15;
    const int m0 = mt * CTAM;
    if (m0 >= count) return;

    extern __shared__ __align__(1024) char smem[];
    const uint32_t sb = smem_u32(smem);
    const int tid  = threadIdx.x;
    const int lane = tid & 31, wid = tid >> 5;
    const int wm = wid >> 2, wn = wid & 3;
    float* shn = (float*)(smem + RS_OFF_HN);

    // A resident: gather ambiguous rows, both planes
    {
#pragma unroll
        for (int q = 0; q < 32; ++q) {
            int i = tid + 256 * q;            // 0..8191 16B units
            int p = i >> 10;
            int r = (i >> 3) & 127;
            int u = i & 7;
            int slot = m0 + r;
            int row = d_amb[slot < count ? slot : count - 1];
            uint4 v = *(const uint4*)(d_A + (size_t)row * 512 + p * 64 + u * 8);
            uint32_t off = (uint32_t)(p * 16384 + ((r >> 3) << 10) + ((r & 7) << 7) + (u << 4));
            *(uint4*)(smem + RS_OFF_A + SWZ(off)) = v;
        }
    }

    float acc[4][8][4];
#pragma unroll
    for (int mi = 0; mi < 4; ++mi)
#pragma unroll
        for (int ni = 0; ni < 8; ++ni)
#pragma unroll
            for (int k = 0; k < 4; ++k) acc[mi][ni][k] = 0.f;
    float minv[8];
    int   mini[8];
#pragma unroll
    for (int i = 0; i < 8; ++i) { minv[i] = 3.4028235e38f; mini[i] = 0; }

    rs_issue_b(sb, 0, ns, tid);
    rs_issue_b(sb, 1, ns, tid);

    const int NITER = 2 * 12;                 // 2 tiles per split
    int tile = 0, c = 0;
    for (int g = 0; g < NITER; ++g) {
        __syncthreads();
        if (g + 2 < NITER) {
            rs_issue_b(sb, g + 2, ns, tid);
            asm volatile("cp.async.wait_group 2;" ::: "memory");
        } else if (g + 1 < NITER) {
            asm volatile("cp.async.wait_group 1;" ::: "memory");
        } else {
            asm volatile("cp.async.wait_group 0;" ::: "memory");
        }
        __syncthreads();

        if (c == 0) shn[tid] = d_half_norm[ns * 512 + tile * CTAN + tid];

        const int apl = (c < 8) ? (c & 3) : (c - 4);
        const uint32_t ab = sb + RS_OFF_A + (uint32_t)apl * 16384;
        const uint32_t bb = sb + RS_OFF_B + (uint32_t)(g % 3) * 32768;
#pragma unroll
        for (int s = 0; s < 4; ++s) {
            uint32_t a[4][4];
#pragma unroll
            for (int mi = 0; mi < 4; ++mi) {
                int r = wm * 64 + mi * 16 + (lane & 7) + ((lane >> 3) & 1) * 8;
                int u = s * 2 + (lane >> 4);
                uint32_t off = ((uint32_t)(r >> 3) << 10) + ((uint32_t)(r & 7) << 7)
                             + ((uint32_t)u << 4);
                asm volatile("ldmatrix.sync.aligned.m8n8.x4.shared.b16 {%0,%1,%2,%3}, [%4];"
                    : "=r"(a[mi][0]), "=r"(a[mi][1]), "=r"(a[mi][2]), "=r"(a[mi][3])
                    : "r"(ab + SWZ(off)));
            }
            uint32_t b[8][2];
#pragma unroll
            for (int nq = 0; nq < 4; ++nq) {
                int r = wn * 64 + nq * 16 + (lane & 7) + ((lane >> 4) & 1) * 8;
                int u = s * 2 + ((lane >> 3) & 1);
                uint32_t off = ((uint32_t)(r >> 3) << 10) + ((uint32_t)(r & 7) << 7)
                             + ((uint32_t)u << 4);
                asm volatile("ldmatrix.sync.aligned.m8n8.x4.shared.b16 {%0,%1,%2,%3}, [%4];"
                    : "=r"(b[2*nq][0]), "=r"(b[2*nq][1]), "=r"(b[2*nq+1][0]), "=r"(b[2*nq+1][1])
                    : "r"(bb + SWZ(off)));
            }
#pragma unroll
            for (int mi = 0; mi < 4; ++mi)
#pragma unroll
                for (int ni = 0; ni < 8; ++ni)
                    asm volatile("mma.sync.aligned.m16n8k16.row.col.f32.f16.f16.f32 "
                        "{%0,%1,%2,%3}, {%4,%5,%6,%7}, {%8,%9}, {%0,%1,%2,%3};"
                        : "+f"(acc[mi][ni][0]), "+f"(acc[mi][ni][1]),
                          "+f"(acc[mi][ni][2]), "+f"(acc[mi][ni][3])
                        : "r"(a[mi][0]), "r"(a[mi][1]), "r"(a[mi][2]), "r"(a[mi][3]),
                          "r"(b[ni][0]), "r"(b[ni][1]));
        }

        if (c == 11) {
#pragma unroll
            for (int ni = 0; ni < 8; ++ni)
#pragma unroll
                for (int c2 = 0; c2 < 2; ++c2) {
                    int coll = wn * 64 + ni * 8 + (lane & 3) * 2 + c2;
                    float hv = shn[coll];
                    int gcol = ns * 512 + tile * CTAN + coll;
#pragma unroll
                    for (int mi = 0; mi < 4; ++mi)
#pragma unroll
                        for (int h = 0; h < 2; ++h) {
                            float sc = hv - acc[mi][ni][h * 2 + c2];
                            int rm = mi * 2 + h;
                            if (sc < minv[rm]) { minv[rm] = sc; mini[rm] = gcol; }
                            acc[mi][ni][h * 2 + c2] = 0.f;
                        }
                }
            tile++; c = 0;
        } else {
            c++;
        }
    }

    __syncthreads();
    float* rv = (float*)(smem + RS_OFF_RV);
    int*   ri = (int*)(smem + RS_OFF_RI);
#pragma unroll
    for (int rm = 0; rm < 8; ++rm) {
        float v = minv[rm]; int ix = mini[rm];
#pragma unroll
        for (int o = 1; o <= 2; o <<= 1) {
            float ov = __shfl_xor_sync(0xffffffffu, v, o);
            int   oi = __shfl_xor_sync(0xffffffffu, ix, o);
            if (ov < v || (ov == v && oi < ix)) { v = ov; ix = oi; }
        }
        if ((lane & 3) == 0) {
            int ml = wm * 64 + (rm >> 1) * 16 + (rm & 1) * 8 + (lane >> 2);
            rv[ml * 4 + wn] = v;
            ri[ml * 4 + wn] = ix;
        }
    }
    __syncthreads();
    if (tid < 128) {
        float v = rv[tid * 4]; int ix = ri[tid * 4];
#pragma unroll
        for (int w = 1; w < 4; ++w) {
            float ov = rv[tid * 4 + w]; int oi = ri[tid * 4 + w];
            if (ov < v || (ov == v && oi < ix)) { v = ov; ix = oi; }
        }
        int slot = m0 + tid;
        if (slot < count) {
            d_resc_v[ns * NN + slot] = v;
            d_resc_i[ns * NN + slot] = ix;
        }
    }
}

__global__ void vq_amb_merge_kernel() {
    int i = blockIdx.x * blockDim.x + threadIdx.x;
    if (i < d_count) {
        float v = d_resc_v[i]; int ix = d_resc_i[i];
#pragma unroll
        for (int s = 1; s < NSPLIT; ++s) {
            float ov = d_resc_v[s * NN + i]; int oi = d_resc_i[s * NN + i];
            if (ov < v || (ov == v && oi < ix)) { v = ov; ix = oi; }
        }
        d_indices[d_amb[i]] = ix;
    }
}

// ---------------------------------------------------------------------------
// gather (+ usage histogram) + stats
// ---------------------------------------------------------------------------
__global__ void vq_gather_kernel(const float* __restrict__ ze,
                                 const float* __restrict__ emb,
                                 float* __restrict__ out) {
    int t = threadIdx.x;
    int m = blockIdx.x * 4 + (t >> 6);
    int l = t & 63;
    int idx = d_indices[m];
    float4 e = *(const float4*)(emb + (size_t)idx * DD + l * 4);
    float4 x = *(const float4*)(ze  + (size_t)m   * DD + l * 4);
    float4 st;
    st.x = x.x + (e.x - x.x); st.y = x.y + (e.y - x.y);
    st.z = x.z + (e.z - x.z); st.w = x.w + (e.w - x.w);
    *(float4*)(out + (size_t)m * DD + l * 4) = st;
    *(float4*)(out + (size_t)NN * DD + (size_t)m * DD + l * 4) = e;
    if (l == 0) {
        out[(size_t)2 * NN * DD + m] = (float)idx;
        atomicAdd(&d_usage[idx], 1);
    }
}

__global__ void vq_stats_kernel(float* __restrict__ out) {
    __shared__ float sH[32];
    __shared__ int   sD[32];
    int t = threadIdx.x;
    float H = 0.f; int dead = 0;
    const float inv_total = 1.0f / (float)NN;
    for (int k = t; k < KK; k += 1024) {
        int u = d_usage[k];
        if (u == 0) dead++;
        else { float p = (float)u * inv_total; H += p * logf(p); }
    }
#pragma unroll
    for (int o = 16; o; o >>= 1) {
        H    += __shfl_xor_sync(0xffffffffu, H, o);
        dead += __shfl_xor_sync(0xffffffffu, dead, o);
    }
    if ((t & 31) == 0) { sH[t >> 5] = H; sD[t >> 5] = dead; }
    __syncthreads();
    if (t == 0) {
        float Ht = 0.f; int dt = 0;
        for (int w = 0; w < 32; w++) { Ht += sH[w]; dt += sD[w]; }
        size_t off = (size_t)2 * NN * DD + NN;
        out[off + 0] = expf(-Ht);
        out[off + 1] = (float)dt / (float)KK;
    }
}

// ---------------------------------------------------------------------------
extern "C" void kernel_launch(void* const* d_in, const int* in_sizes, int n_in,
                              void* d_out, int out_size) {
    const float* ze  = (const float*)d_in[0];
    const float* emb = (const float*)d_in[1];
    float* out = (float*)d_out;

    cudaFuncSetAttribute(vq_pass1_kernel, cudaFuncAttributeMaxDynamicSharedMemorySize,
                         P1_SMEM);
    cudaFuncSetAttribute(vq_rescue_kernel, cudaFuncAttributeMaxDynamicSharedMemorySize,
                         RS_SMEM);

    vq_split_ze<<<NN / 8, 256>>>(ze);
    vq_split_emb<<<KK / 8, 256>>>(emb);
    vq_pass1_kernel<<<NN / CTAM, 256, P1_SMEM>>>();
    vq_rescue_kernel<<<(NN / CTAM) * NSPLIT, 256, RS_SMEM>>>();
    vq_amb_merge_kernel<<<NN / 256, 256>>>();
    vq_gather_kernel<<<NN / 4, 256>>>(ze, emb, out);
    vq_stats_kernel<<<1, 1024>>>(out);
}

// round 9
// speedup vs baseline: 6.1378x; 1.2003x over previous
#include <cuda_runtime.h>
#include <cuda_fp16.h>
#include <cstdint>

#define DD   256
#define KK   8192
#define NN   32768
#define CTAM 128
#define NSPLIT 16                 // rescue N-splits (512 codes each)

// ---- pass1 smem layout (A = a0 only, 4 planes; CTAN=128; 2-stage 16KB B ring)
#define P1_CTAN   128
#define P1_OFF_A  0               // 4 x 16384 = 65536
#define P1_OFF_B  65536           // 2 stages x 16384 = 32768
#define P1_OFF_HN 98304           // 128 floats
#define P1_SMEM   98816
#define P1_OFF_RV P1_OFF_B
#define P1_OFF_RI (P1_OFF_B + 2048)
#define P1_OFF_R2 (P1_OFF_B + 4096)

// ---- rescue smem layout (A = [a0|a1], 8 planes; 3-stage 32KB ring; CTAN=256)
#define CTAN 256
#define RS_OFF_A  0               // 8 x 16384 = 131072
#define RS_OFF_B  131072          // 3 stages x 32768
#define RS_OFF_HN 229376
#define RS_SMEM   230400
#define RS_OFF_RV RS_OFF_B
#define RS_OFF_RI (RS_OFF_B + 2048)

#define SWZ(x) ((x) ^ (((x) >> 3) & 0x70))

// Scratch (no allocations allowed)
__device__ float d_half_norm[KK];
__device__ float d_a0norm[NN];
__device__ float d_rxnorm[NN];
__device__ int   d_usage[KK];
__device__ int   d_indices[NN];
__device__ int   d_count;
__device__ int   d_b0max_bits;
__device__ int   d_remax_bits;
__device__ int   d_amb[NN];
__device__ float d_resc_v[NSPLIT * NN];
__device__ int   d_resc_i[NSPLIT * NN];
__device__ __half d_A[(size_t)NN * 512];   // [a0(256) | a1(256)] per row
__device__ __half d_B[(size_t)KK * 512];   // [b0(256) | b1(256)] per row

__device__ __forceinline__ uint32_t smem_u32(const void* p) {
    uint32_t a;
    asm("{ .reg .u64 t; cvta.to.shared.u64 t, %1; cvt.u32.u64 %0, t; }" : "=r"(a) : "l"(p));
    return a;
}

// ---------------------------------------------------------------------------
// Fused splits: exact 2-way fp16 split + exact split-part norms (warp per row)
// ---------------------------------------------------------------------------
__global__ void vq_split_ze(const float* __restrict__ src) {
    if (blockIdx.x == 0 && threadIdx.x == 0) {
        d_count = 0; d_b0max_bits = 0; d_remax_bits = 0;
    }
    int row  = blockIdx.x * 8 + (threadIdx.x >> 5);
    int lane = threadIdx.x & 31;
    const float4* x4 = (const float4*)(src + (size_t)row * DD + lane * 8);
    float4 v0 = x4[0], v1 = x4[1];
    float vv[8] = {v0.x, v0.y, v0.z, v0.w, v1.x, v1.y, v1.z, v1.w};
    __half h0[8], h1[8];
    float s0 = 0.f, s1 = 0.f;
#pragma unroll
    for (int i = 0; i < 8; ++i) {
        h0[i] = __float2half_rn(vv[i]);
        float f0 = __half2float(h0[i]);
        h1[i] = __float2half_rn(vv[i] - f0);
        float f1 = __half2float(h1[i]);
        s0 += f0 * f0;
        s1 += f1 * f1;
    }
#pragma unroll
    for (int o = 16; o; o >>= 1) {
        s0 += __shfl_xor_sync(0xffffffffu, s0, o);
        s1 += __shfl_xor_sync(0xffffffffu, s1, o);
    }
    if (lane == 0) { d_a0norm[row] = sqrtf(s0); d_rxnorm[row] = sqrtf(s1); }
    *(uint4*)(d_A + (size_t)row * 512 + lane * 8)       = *(uint4*)h0;
    *(uint4*)(d_A + (size_t)row * 512 + 256 + lane * 8) = *(uint4*)h1;
}
__global__ void vq_split_emb(const float* __restrict__ src) {
    int row  = blockIdx.x * 8 + (threadIdx.x >> 5);
    int lane = threadIdx.x & 31;
    const float4* x4 = (const float4*)(src + (size_t)row * DD + lane * 8);
    float4 v0 = x4[0], v1 = x4[1];
    float vv[8] = {v0.x, v0.y, v0.z, v0.w, v1.x, v1.y, v1.z, v1.w};
    __half h0[8], h1[8];
    float s = 0.f, s0 = 0.f, s1 = 0.f;
#pragma unroll
    for (int i = 0; i < 8; ++i) {
        h0[i] = __float2half_rn(vv[i]);
        float f0 = __half2float(h0[i]);
        h1[i] = __float2half_rn(vv[i] - f0);
        float f1 = __half2float(h1[i]);
        s  += vv[i] * vv[i];
        s0 += f0 * f0;
        s1 += f1 * f1;
    }
#pragma unroll
    for (int o = 16; o; o >>= 1) {
        s  += __shfl_xor_sync(0xffffffffu, s, o);
        s0 += __shfl_xor_sync(0xffffffffu, s0, o);
        s1 += __shfl_xor_sync(0xffffffffu, s1, o);
    }
    if (lane == 0) {
        d_half_norm[row] = 0.5f * s;
        atomicMax(&d_b0max_bits, __float_as_int(sqrtf(s0)));
        atomicMax(&d_remax_bits, __float_as_int(sqrtf(s1)));
    }
    *(uint4*)(d_B + (size_t)row * 512 + lane * 8)       = *(uint4*)h0;
    *(uint4*)(d_B + (size_t)row * 512 + 256 + lane * 8) = *(uint4*)h1;
    int g = blockIdx.x * blockDim.x + threadIdx.x;
    if (g < KK) d_usage[g] = 0;
}

// ---------------------------------------------------------------------------
// Pass 1: single-product (a0*b0) GEMM + min1/min2 + certification.
// CTAN=128, warp tile 64x32, occupancy 2.
// ---------------------------------------------------------------------------
__device__ __forceinline__ void p1_issue(uint32_t sb, int g2, int tid) {
    const int t2 = g2 >> 2, seg = g2 & 3;               // b0 segs 0-3
    const __half* src = d_B + (size_t)(t2 * P1_CTAN) * 512 + seg * 64;
    uint32_t db = sb + P1_OFF_B + (uint32_t)(g2 & 1) * 16384;
#pragma unroll
    for (int j = 0; j < 4; ++j) {
        int i = tid + 256 * j;                          // 0..1023 16B units
        int r = i >> 3, u = i & 7;
        const void* gp = (const void*)(src + (size_t)r * 512 + u * 8);
        uint32_t off = (uint32_t)(((r >> 3) << 10) + ((r & 7) << 7) + (u << 4));
        asm volatile("cp.async.cg.shared.global [%0], [%1], 16;"
                     :: "r"(db + SWZ(off)), "l"(gp));
    }
    asm volatile("cp.async.commit_group;" ::: "memory");
}

__global__ __launch_bounds__(256, 2) void vq_pass1_kernel() {
    extern __shared__ __align__(1024) char smem[];
    const uint32_t sb = smem_u32(smem);
    const int tid  = threadIdx.x;
    const int lane = tid & 31, wid = tid >> 5;
    const int wm = wid >> 2, wn = wid & 3;              // 2m x 4n warp grid
    const int m0 = blockIdx.x * CTAM;
    float* shn = (float*)(smem + P1_OFF_HN);

    // A resident: a0 only, 4 planes
    {
        const __half* Arow = d_A + (size_t)m0 * 512;
#pragma unroll
        for (int q = 0; q < 16; ++q) {
            int i = tid + 256 * q;            // 0..4095 16B units
            int p = i >> 10;
            int r = (i >> 3) & 127;
            int u = i & 7;
            uint4 v = *(const uint4*)(Arow + (size_t)r * 512 + p * 64 + u * 8);
            uint32_t off = (uint32_t)(p * 16384 + ((r >> 3) << 10) + ((r & 7) << 7) + (u << 4));
            *(uint4*)(smem + P1_OFF_A + SWZ(off)) = v;
        }
    }

    float acc[4][4][4];
#pragma unroll
    for (int mi = 0; mi < 4; ++mi)
#pragma unroll
        for (int ni = 0; ni < 4; ++ni)
#pragma unroll
            for (int k = 0; k < 4; ++k) acc[mi][ni][k] = 0.f;
    float m1[8], m2[8];
    int   i1[8];
#pragma unroll
    for (int i = 0; i < 8; ++i) { m1[i] = 3.4028235e38f; m2[i] = 3.4028235e38f; i1[i] = 0; }

    p1_issue(sb, 0, tid);

    const int NITER = (KK / P1_CTAN) * 4;               // 64 tiles x 4 chunks = 256
    for (int g = 0; g < NITER; ++g) {
        __syncthreads();
        if (g + 1 < NITER) {
            p1_issue(sb, g + 1, tid);
            asm volatile("cp.async.wait_group 1;" ::: "memory");
        } else {
            asm volatile("cp.async.wait_group 0;" ::: "memory");
        }
        __syncthreads();

        const int tile = g >> 2, c = g & 3;
        if (c == 0 && tid < 128) shn[tid] = d_half_norm[tile * P1_CTAN + tid];

        const uint32_t ab = sb + P1_OFF_A + (uint32_t)c * 16384;
        const uint32_t bb = sb + P1_OFF_B + (uint32_t)(g & 1) * 16384;
#pragma unroll
        for (int s = 0; s < 4; ++s) {
            uint32_t a[4][4];
#pragma unroll
            for (int mi = 0; mi < 4; ++mi) {
                int r = wm * 64 + mi * 16 + (lane & 7) + ((lane >> 3) & 1) * 8;
                int u = s * 2 + (lane >> 4);
                uint32_t off = ((uint32_t)(r >> 3) << 10) + ((uint32_t)(r & 7) << 7)
                             + ((uint32_t)u << 4);
                asm volatile("ldmatrix.sync.aligned.m8n8.x4.shared.b16 {%0,%1,%2,%3}, [%4];"
                    : "=r"(a[mi][0]), "=r"(a[mi][1]), "=r"(a[mi][2]), "=r"(a[mi][3])
                    : "r"(ab + SWZ(off)));
            }
            uint32_t b[4][2];
#pragma unroll
            for (int nq = 0; nq < 2; ++nq) {
                int r = wn * 32 + nq * 16 + (lane & 7) + ((lane >> 4) & 1) * 8;
                int u = s * 2 + ((lane >> 3) & 1);
                uint32_t off = ((uint32_t)(r >> 3) << 10) + ((uint32_t)(r & 7) << 7)
                             + ((uint32_t)u << 4);
                asm volatile("ldmatrix.sync.aligned.m8n8.x4.shared.b16 {%0,%1,%2,%3}, [%4];"
                    : "=r"(b[2*nq][0]), "=r"(b[2*nq][1]), "=r"(b[2*nq+1][0]), "=r"(b[2*nq+1][1])
                    : "r"(bb + SWZ(off)));
            }
#pragma unroll
            for (int mi = 0; mi < 4; ++mi)
#pragma unroll
                for (int ni = 0; ni < 4; ++ni)
                    asm volatile("mma.sync.aligned.m16n8k16.row.col.f32.f16.f16.f32 "
                        "{%0,%1,%2,%3}, {%4,%5,%6,%7}, {%8,%9}, {%0,%1,%2,%3};"
                        : "+f"(acc[mi][ni][0]), "+f"(acc[mi][ni][1]),
                          "+f"(acc[mi][ni][2]), "+f"(acc[mi][ni][3])
                        : "r"(a[mi][0]), "r"(a[mi][1]), "r"(a[mi][2]), "r"(a[mi][3]),
                          "r"(b[ni][0]), "r"(b[ni][1]));
        }

        if (c == 3) {
#pragma unroll
            for (int ni = 0; ni < 4; ++ni)
#pragma unroll
                for (int c2 = 0; c2 < 2; ++c2) {
                    int coll = wn * 32 + ni * 8 + (lane & 3) * 2 + c2;
                    float hv = shn[coll];
                    int gcol = tile * P1_CTAN + coll;
#pragma unroll
                    for (int mi = 0; mi < 4; ++mi)
#pragma unroll
                        for (int h = 0; h < 2; ++h) {
                            float sc = hv - acc[mi][ni][h * 2 + c2];
                            int rm = mi * 2 + h;
                            if (sc < m1[rm]) { m2[rm] = m1[rm]; m1[rm] = sc; i1[rm] = gcol; }
                            else if (sc < m2[rm]) { m2[rm] = sc; }
                            acc[mi][ni][h * 2 + c2] = 0.f;
                        }
                }
        }
    }

    // reduce (m1,i1,m2) per row; scratch aliases B ring
    __syncthreads();
    float* rv = (float*)(smem + P1_OFF_RV);
    int*   ri = (int*)(smem + P1_OFF_RI);
    float* r2 = (float*)(smem + P1_OFF_R2);
#pragma unroll
    for (int rm = 0; rm < 8; ++rm) {
        float v = m1[rm], v2 = m2[rm];
        int ix = i1[rm];
#pragma unroll
        for (int o = 1; o <= 2; o <<= 1) {
            float ov  = __shfl_xor_sync(0xffffffffu, v, o);
            int   oi  = __shfl_xor_sync(0xffffffffu, ix, o);
            float ov2 = __shfl_xor_sync(0xffffffffu, v2, o);
            if (ov < v || (ov == v && oi < ix)) {
                v2 = fminf(v, ov2); v = ov; ix = oi;
            } else {
                v2 = fminf(v2, ov);
            }
        }
        if ((lane & 3) == 0) {
            int ml = wm * 64 + (rm >> 1) * 16 + (rm & 1) * 8 + (lane >> 2);
            rv[ml * 4 + wn] = v; ri[ml * 4 + wn] = ix; r2[ml * 4 + wn] = v2;
        }
    }
    __syncthreads();
    if (tid < 128) {
        float v = rv[tid * 4], v2 = r2[tid * 4];
        int ix = ri[tid * 4];
#pragma unroll
        for (int w = 1; w < 4; ++w) {
            float ov = rv[tid * 4 + w], ov2 = r2[tid * 4 + w];
            int oi = ri[tid * 4 + w];
            if (ov < v || (ov == v && oi < ix)) {
                v2 = fminf(v, ov2); v = ov; ix = oi;
            } else {
                v2 = fminf(v2, ov);
            }
        }
        const int row = m0 + tid;
        d_indices[row] = ix;
        // certified Cauchy-Schwarz bound with exact split-part norms:
        // |score_p1 - score_rescue| <= ||a0||*max||b1|| + ||a1||*max||b0||
        float thr = (d_a0norm[row] * __int_as_float(d_remax_bits)
                   + d_rxnorm[row] * __int_as_float(d_b0max_bits)) * 1.01f + 1e-4f;
        if (!(v2 - v > thr)) {
            int pos = atomicAdd(&d_count, 1);
            d_amb[pos] = row;
        }
    }
}

// ---------------------------------------------------------------------------
// Rescue: exact 3-product GEMM over ambiguous rows, N-split by 16 (512 codes)
// ---------------------------------------------------------------------------
__device__ __forceinline__ void rs_issue_b(uint32_t sb, int g2, int ns, int tid) {
    const int t2 = g2 / 12;
    const int c2 = g2 - t2 * 12;
    const int seg = (c2 < 8) ? c2 : (c2 - 8);
    const __half* src = d_B + (size_t)(ns * 512 + t2 * CTAN) * 512 + seg * 64;
    uint32_t db = sb + RS_OFF_B + (uint32_t)(g2 % 3) * 32768;
#pragma unroll
    for (int j = 0; j < 8; ++j) {
        int i = tid + 256 * j;
        int r = i >> 3, u = i & 7;
        const void* gp = (const void*)(src + (size_t)r * 512 + u * 8);
        uint32_t off = (uint32_t)(((r >> 3) << 10) + ((r & 7) << 7) + (u << 4));
        asm volatile("cp.async.cg.shared.global [%0], [%1], 16;"
                     :: "r"(db + SWZ(off)), "l"(gp));
    }
    asm volatile("cp.async.commit_group;" ::: "memory");
}

__global__ __launch_bounds__(256, 1) void vq_rescue_kernel() {
    const int count = d_count;
    const int mt = blockIdx.x >> 4;
    const int ns = blockIdx.x & 15;
    const int m0 = mt * CTAM;
    if (m0 >= count) return;

    extern __shared__ __align__(1024) char smem[];
    const uint32_t sb = smem_u32(smem);
    const int tid  = threadIdx.x;
    const int lane = tid & 31, wid = tid >> 5;
    const int wm = wid >> 2, wn = wid & 3;
    float* shn = (float*)(smem + RS_OFF_HN);

    // A resident: gather ambiguous rows, both planes
    {
#pragma unroll
        for (int q = 0; q < 32; ++q) {
            int i = tid + 256 * q;            // 0..8191 16B units
            int p = i >> 10;
            int r = (i >> 3) & 127;
            int u = i & 7;
            int slot = m0 + r;
            int row = d_amb[slot < count ? slot : count - 1];
            uint4 v = *(const uint4*)(d_A + (size_t)row * 512 + p * 64 + u * 8);
            uint32_t off = (uint32_t)(p * 16384 + ((r >> 3) << 10) + ((r & 7) << 7) + (u << 4));
            *(uint4*)(smem + RS_OFF_A + SWZ(off)) = v;
        }
    }

    float acc[4][8][4];
#pragma unroll
    for (int mi = 0; mi < 4; ++mi)
#pragma unroll
        for (int ni = 0; ni < 8; ++ni)
#pragma unroll
            for (int k = 0; k < 4; ++k) acc[mi][ni][k] = 0.f;
    float minv[8];
    int   mini[8];
#pragma unroll
    for (int i = 0; i < 8; ++i) { minv[i] = 3.4028235e38f; mini[i] = 0; }

    rs_issue_b(sb, 0, ns, tid);
    rs_issue_b(sb, 1, ns, tid);

    const int NITER = 2 * 12;                 // 2 tiles per split
    int tile = 0, c = 0;
    for (int g = 0; g < NITER; ++g) {
        __syncthreads();
        if (g + 2 < NITER) {
            rs_issue_b(sb, g + 2, ns, tid);
            asm volatile("cp.async.wait_group 2;" ::: "memory");
        } else if (g + 1 < NITER) {
            asm volatile("cp.async.wait_group 1;" ::: "memory");
        } else {
            asm volatile("cp.async.wait_group 0;" ::: "memory");
        }
        __syncthreads();

        if (c == 0) shn[tid] = d_half_norm[ns * 512 + tile * CTAN + tid];

        const int apl = (c < 8) ? (c & 3) : (c - 4);
        const uint32_t ab = sb + RS_OFF_A + (uint32_t)apl * 16384;
        const uint32_t bb = sb + RS_OFF_B + (uint32_t)(g % 3) * 32768;
#pragma unroll
        for (int s = 0; s < 4; ++s) {
            uint32_t a[4][4];
#pragma unroll
            for (int mi = 0; mi < 4; ++mi) {
                int r = wm * 64 + mi * 16 + (lane & 7) + ((lane >> 3) & 1) * 8;
                int u = s * 2 + (lane >> 4);
                uint32_t off = ((uint32_t)(r >> 3) << 10) + ((uint32_t)(r & 7) << 7)
                             + ((uint32_t)u << 4);
                asm volatile("ldmatrix.sync.aligned.m8n8.x4.shared.b16 {%0,%1,%2,%3}, [%4];"
                    : "=r"(a[mi][0]), "=r"(a[mi][1]), "=r"(a[mi][2]), "=r"(a[mi][3])
                    : "r"(ab + SWZ(off)));
            }
            uint32_t b[8][2];
#pragma unroll
            for (int nq = 0; nq < 4; ++nq) {
                int r = wn * 64 + nq * 16 + (lane & 7) + ((lane >> 4) & 1) * 8;
                int u = s * 2 + ((lane >> 3) & 1);
                uint32_t off = ((uint32_t)(r >> 3) << 10) + ((uint32_t)(r & 7) << 7)
                             + ((uint32_t)u << 4);
                asm volatile("ldmatrix.sync.aligned.m8n8.x4.shared.b16 {%0,%1,%2,%3}, [%4];"
                    : "=r"(b[2*nq][0]), "=r"(b[2*nq][1]), "=r"(b[2*nq+1][0]), "=r"(b[2*nq+1][1])
                    : "r"(bb + SWZ(off)));
            }
#pragma unroll
            for (int mi = 0; mi < 4; ++mi)
#pragma unroll
                for (int ni = 0; ni < 8; ++ni)
                    asm volatile("mma.sync.aligned.m16n8k16.row.col.f32.f16.f16.f32 "
                        "{%0,%1,%2,%3}, {%4,%5,%6,%7}, {%8,%9}, {%0,%1,%2,%3};"
                        : "+f"(acc[mi][ni][0]), "+f"(acc[mi][ni][1]),
                          "+f"(acc[mi][ni][2]), "+f"(acc[mi][ni][3])
                        : "r"(a[mi][0]), "r"(a[mi][1]), "r"(a[mi][2]), "r"(a[mi][3]),
                          "r"(b[ni][0]), "r"(b[ni][1]));
        }

        if (c == 11) {
#pragma unroll
            for (int ni = 0; ni < 8; ++ni)
#pragma unroll
                for (int c2 = 0; c2 < 2; ++c2) {
                    int coll = wn * 64 + ni * 8 + (lane & 3) * 2 + c2;
                    float hv = shn[coll];
                    int gcol = ns * 512 + tile * CTAN + coll;
#pragma unroll
                    for (int mi = 0; mi < 4; ++mi)
#pragma unroll
                        for (int h = 0; h < 2; ++h) {
                            float sc = hv - acc[mi][ni][h * 2 + c2];
                            int rm = mi * 2 + h;
                            if (sc < minv[rm]) { minv[rm] = sc; mini[rm] = gcol; }
                            acc[mi][ni][h * 2 + c2] = 0.f;
                        }
                }
            tile++; c = 0;
        } else {
            c++;
        }
    }

    __syncthreads();
    float* rv = (float*)(smem + RS_OFF_RV);
    int*   ri = (int*)(smem + RS_OFF_RI);
#pragma unroll
    for (int rm = 0; rm < 8; ++rm) {
        float v = minv[rm]; int ix = mini[rm];
#pragma unroll
        for (int o = 1; o <= 2; o <<= 1) {
            float ov = __shfl_xor_sync(0xffffffffu, v, o);
            int   oi = __shfl_xor_sync(0xffffffffu, ix, o);
            if (ov < v || (ov == v && oi < ix)) { v = ov; ix = oi; }
        }
        if ((lane & 3) == 0) {
            int ml = wm * 64 + (rm >> 1) * 16 + (rm & 1) * 8 + (lane >> 2);
            rv[ml * 4 + wn] = v;
            ri[ml * 4 + wn] = ix;
        }
    }
    __syncthreads();
    if (tid < 128) {
        float v = rv[tid * 4]; int ix = ri[tid * 4];
#pragma unroll
        for (int w = 1; w < 4; ++w) {
            float ov = rv[tid * 4 + w]; int oi = ri[tid * 4 + w];
            if (ov < v || (ov == v && oi < ix)) { v = ov; ix = oi; }
        }
        int slot = m0 + tid;
        if (slot < count) {
            d_resc_v[ns * NN + slot] = v;
            d_resc_i[ns * NN + slot] = ix;
        }
    }
}

__global__ void vq_amb_merge_kernel() {
    int i = blockIdx.x * blockDim.x + threadIdx.x;
    if (i < d_count) {
        float v = d_resc_v[i]; int ix = d_resc_i[i];
#pragma unroll
        for (int s = 1; s < NSPLIT; ++s) {
            float ov = d_resc_v[s * NN + i]; int oi = d_resc_i[s * NN + i];
            if (ov < v || (ov == v && oi < ix)) { v = ov; ix = oi; }
        }
        d_indices[d_amb[i]] = ix;
    }
}

// ---------------------------------------------------------------------------
// gather (+ usage histogram) + stats
// ---------------------------------------------------------------------------
__global__ void vq_gather_kernel(const float* __restrict__ ze,
                                 const float* __restrict__ emb,
                                 float* __restrict__ out) {
    int t = threadIdx.x;
    int m = blockIdx.x * 4 + (t >> 6);
    int l = t & 63;
    int idx = d_indices[m];
    float4 e = *(const float4*)(emb + (size_t)idx * DD + l * 4);
    float4 x = *(const float4*)(ze  + (size_t)m   * DD + l * 4);
    float4 st;
    st.x = x.x + (e.x - x.x); st.y = x.y + (e.y - x.y);
    st.z = x.z + (e.z - x.z); st.w = x.w + (e.w - x.w);
    *(float4*)(out + (size_t)m * DD + l * 4) = st;
    *(float4*)(out + (size_t)NN * DD + (size_t)m * DD + l * 4) = e;
    if (l == 0) {
        out[(size_t)2 * NN * DD + m] = (float)idx;
        atomicAdd(&d_usage[idx], 1);
    }
}

__global__ void vq_stats_kernel(float* __restrict__ out) {
    __shared__ float sH[32];
    __shared__ int   sD[32];
    int t = threadIdx.x;
    float H = 0.f; int dead = 0;
    const float inv_total = 1.0f / (float)NN;
    for (int k = t; k < KK; k += 1024) {
        int u = d_usage[k];
        if (u == 0) dead++;
        else { float p = (float)u * inv_total; H += p * logf(p); }
    }
#pragma unroll
    for (int o = 16; o; o >>= 1) {
        H    += __shfl_xor_sync(0xffffffffu, H, o);
        dead += __shfl_xor_sync(0xffffffffu, dead, o);
    }
    if ((t & 31) == 0) { sH[t >> 5] = H; sD[t >> 5] = dead; }
    __syncthreads();
    if (t == 0) {
        float Ht = 0.f; int dt = 0;
        for (int w = 0; w < 32; w++) { Ht += sH[w]; dt += sD[w]; }
        size_t off = (size_t)2 * NN * DD + NN;
        out[off + 0] = expf(-Ht);
        out[off + 1] = (float)dt / (float)KK;
    }
}

// ---------------------------------------------------------------------------
extern "C" void kernel_launch(void* const* d_in, const int* in_sizes, int n_in,
                              void* d_out, int out_size) {
    const float* ze  = (const float*)d_in[0];
    const float* emb = (const float*)d_in[1];
    float* out = (float*)d_out;

    cudaFuncSetAttribute(vq_pass1_kernel, cudaFuncAttributeMaxDynamicSharedMemorySize,
                         P1_SMEM);
    cudaFuncSetAttribute(vq_rescue_kernel, cudaFuncAttributeMaxDynamicSharedMemorySize,
                         RS_SMEM);

    vq_split_ze<<<NN / 8, 256>>>(ze);
    vq_split_emb<<<KK / 8, 256>>>(emb);
    vq_pass1_kernel<<<NN / CTAM, 256, P1_SMEM>>>();
    vq_rescue_kernel<<<(NN / CTAM) * NSPLIT, 256, RS_SMEM>>>();
    vq_amb_merge_kernel<<<NN / 256, 256>>>();
    vq_gather_kernel<<<NN / 4, 256>>>(ze, emb, out);
    vq_stats_kernel<<<1, 1024>>>(out);
}